// round 10
// baseline (speedup 1.0000x reference)
#include <cuda_runtime.h>
#include <cuda_bf16.h>
#include <cstdint>

#define NN   8192
#define EE   65536
#define IND  128
#define HID  64
#define RDIM 4096   // HID*HID

// ---------------- static scratch (no allocs allowed) ----------------
__device__ float g_A[(size_t)NN * RDIM];       // A' [n][d*64 + j], BN folded (128 MB)
__device__ float g_S[NN * 192];                // per-node: p2 | qs | qd
__device__ float g_b1f[RDIM];
__device__ float g_bsm[192];
__device__ float g_Call[HID];
__device__ __nv_bfloat16 g_Hhi[(size_t)NN * IND];
__device__ __nv_bfloat16 g_Hlo[(size_t)NN * IND];
__device__ __nv_bfloat16 g_Whi[(size_t)RDIM * IND];
__device__ __nv_bfloat16 g_Wlo[(size_t)RDIM * IND];
__device__ __nv_bfloat16 g_Wsmhi[192 * IND];
__device__ __nv_bfloat16 g_Wsmlo[192 * IND];
__device__ int   g_hist[NN];
__device__ int   g_off[NN + 1];
__device__ int   g_cursor[NN];
__device__ int   g_sorted[EE];

// ---------------- helpers ----------------
__device__ __forceinline__ uint32_t smem_u32(const void* p) {
    uint32_t a;
    asm("{ .reg .u64 t; cvta.to.shared.u64 t, %1; cvt.u32.u64 %0, t; }" : "=r"(a) : "l"(p));
    return a;
}
__device__ __forceinline__ void ldm4(uint32_t* r, uint32_t addr) {
    asm volatile("ldmatrix.sync.aligned.m8n8.x4.shared.b16 {%0,%1,%2,%3}, [%4];"
                 : "=r"(r[0]), "=r"(r[1]), "=r"(r[2]), "=r"(r[3]) : "r"(addr));
}
__device__ __forceinline__ void mma16816(float* d, const uint32_t* a, uint32_t b0, uint32_t b1) {
    asm volatile(
        "mma.sync.aligned.m16n8k16.row.col.f32.bf16.bf16.f32 "
        "{%0,%1,%2,%3}, {%4,%5,%6,%7}, {%8,%9}, {%0,%1,%2,%3};"
        : "+f"(d[0]), "+f"(d[1]), "+f"(d[2]), "+f"(d[3])
        : "r"(a[0]), "r"(a[1]), "r"(a[2]), "r"(a[3]), "r"(b0), "r"(b1));
}
// sync tile load: rows of 128 bf16 (256B), 16B chunk ch swizzled (ch^row)&7
__device__ __forceinline__ void ld_tile_n(const __nv_bfloat16* __restrict__ src, int row0,
                                          char* dst, int tid, int nrows) {
    for (int idx = tid; idx < nrows * 16; idx += 256) {
        int row = idx >> 4, ch = idx & 15;
        uint4 v = *(const uint4*)(src + (size_t)(row0 + row) * IND + ch * 8);
        *(uint4*)(dst + row * 256 + ((((ch & 7) ^ (row & 7)) << 4) + ((ch & 8) << 4))) = v;
    }
}

// ---------------- fold1: one block per d; writes bf16 split of W1f + b1f ---------------
__global__ __launch_bounds__(256) void k_fold1(const float* __restrict__ p1w,
                                               const float* __restrict__ p1b,
                                               const float* __restrict__ e3w,
                                               const float* __restrict__ gam,
                                               const float* __restrict__ var) {
    __shared__ float hp[64 * 128];   // p1w rows (j<<6)|d
    __shared__ float pb[64];
    __shared__ float ss[64];
    int d = blockIdx.x, tid = threadIdx.x;
    for (int idx = tid; idx < 64 * 128; idx += 256) {
        int j = idx >> 7, k = idx & 127;
        hp[idx] = p1w[(size_t)((j << 6) | d) * IND + k];
    }
    if (tid < 64) {
        pb[tid] = p1b[(tid << 6) | d];
        ss[tid] = gam[tid] * rsqrtf(var[tid] + 1e-5f);
    }
    __syncthreads();
    int k = tid & 127, jp0 = tid >> 7;
    for (int jp = jp0; jp < 64; jp += 2) {
        const float* er = e3w + jp * 64;    // broadcast per warp, L1-cached
        float acc = 0.f;
#pragma unroll 8
        for (int j = 0; j < 64; ++j) acc += er[j] * hp[j * 128 + k];
        float v = ss[jp] * acc;
        size_t ro = (size_t)((d << 6) | jp) * IND + k;
        __nv_bfloat16 hi = __float2bfloat16(v);
        g_Whi[ro] = hi;
        g_Wlo[ro] = __float2bfloat16(v - __bfloat162float(hi));
        if (k == 0) {
            float b = 0.f;
            for (int j = 0; j < 64; ++j) b += er[j] * pb[j];
            g_b1f[(d << 6) | jp] = ss[jp] * b;
        }
    }
}

// ---------------- fold2: small weights bf16 split [c][k] ----------------
__global__ void k_fold2(const float* __restrict__ p2w, const float* __restrict__ p2b,
                        const float* __restrict__ convw, const float* __restrict__ e2w,
                        const float* __restrict__ gam, const float* __restrict__ var) {
    int c = blockIdx.x;            // 0..191
    int k = threadIdx.x;           // 0..127
    float val;
    if (c < 64) {
        val = p2w[c * IND + k];
        if (k == 0) g_bsm[c] = p2b[c];
    } else {
        int j  = (c - 64) & 63;
        int cc = (c >= 128) ? 1 : 0;
        float s = gam[j] * rsqrtf(var[j] + 1e-5f);
        float a = 0.f;
#pragma unroll
        for (int u = 0; u < 3; ++u) {
            int i = k - u + 1;
            if (i >= 0 && i < IND) a += convw[cc * 3 + u] * e2w[j * IND + i];
        }
        val = s * a;
        if (k == 0) g_bsm[c] = 0.f;
    }
    __nv_bfloat16 hi = __float2bfloat16(val);
    g_Wsmhi[c * IND + k] = hi;
    g_Wsmlo[c * IND + k] = __float2bfloat16(val - __bfloat162float(hi));
}

__global__ void k_call(const float* __restrict__ e2w, const float* __restrict__ e2b,
                       const float* __restrict__ e3b, const float* __restrict__ convb,
                       const float* __restrict__ gam, const float* __restrict__ bet,
                       const float* __restrict__ mean, const float* __restrict__ var) {
    int j = threadIdx.x;
    float s = gam[j] * rsqrtf(var[j] + 1e-5f);
    float t = bet[j] - mean[j] * s;
    float rs = 0.f;
    for (int i = 0; i < IND; ++i) rs += e2w[j * IND + i];
    g_Call[j] = s * (convb[0] * rs + e2b[j] + e3b[j]) + t;
}

// ---------------- bf16 split of h, 4 elements/thread ----------------
__global__ void k_convert_h(const float* __restrict__ h) {
    int i = blockIdx.x * 256 + threadIdx.x;   // grid 1024 -> 262144, x4 elems
    float4 v = ((const float4*)h)[i];
    __nv_bfloat16 h0 = __float2bfloat16(v.x), h1 = __float2bfloat16(v.y);
    __nv_bfloat16 h2 = __float2bfloat16(v.z), h3 = __float2bfloat16(v.w);
    __nv_bfloat162* Hh = (__nv_bfloat162*)g_Hhi;
    __nv_bfloat162* Hl = (__nv_bfloat162*)g_Hlo;
    Hh[2 * i]     = __nv_bfloat162(h0, h1);
    Hh[2 * i + 1] = __nv_bfloat162(h2, h3);
    Hl[2 * i]     = __nv_bfloat162(__float2bfloat16(v.x - __bfloat162float(h0)),
                                   __float2bfloat16(v.y - __bfloat162float(h1)));
    Hl[2 * i + 1] = __nv_bfloat162(__float2bfloat16(v.z - __bfloat162float(h2)),
                                   __float2bfloat16(v.w - __bfloat162float(h3)));
}

// ---------------- small GEMM on tensor cores: S = h @ Wsm^T + bias ----------------
// CTA tile M=128 x N=192, full K=128; grid = 64 (m only). 8 warps 2x4, warp 64x48.
#define SG_A_HI 0
#define SG_A_LO 32768
#define SG_B_HI 65536
#define SG_B_LO 114688
#define SG_SMEM 163840

__global__ __launch_bounds__(256) void k_sgemm_mma() {
    extern __shared__ char smem[];
    int tid = threadIdx.x;
    int warp = tid >> 5, lane = tid & 31;
    int m0 = blockIdx.x * 128;

    ld_tile_n(g_Hhi,   m0, smem + SG_A_HI, tid, 128);
    ld_tile_n(g_Hlo,   m0, smem + SG_A_LO, tid, 128);
    ld_tile_n(g_Wsmhi, 0,  smem + SG_B_HI, tid, 192);
    ld_tile_n(g_Wsmlo, 0,  smem + SG_B_LO, tid, 192);
    __syncthreads();

    int wm = warp & 1, wn = warp >> 1;   // 2 x 4
    uint32_t sbase = smem_u32(smem);
    float acc[4][6][4];
#pragma unroll
    for (int mt = 0; mt < 4; ++mt)
#pragma unroll
        for (int nt = 0; nt < 6; ++nt)
#pragma unroll
            for (int i = 0; i < 4; ++i) acc[mt][nt][i] = 0.f;

    int rbase = lane & 15;
    int khalf = (lane >> 4) << 3;

#pragma unroll 1
    for (int pass = 0; pass < 3; ++pass) {
        uint32_t aBase = sbase + ((pass == 2) ? SG_A_LO : SG_A_HI);
        uint32_t bBase = sbase + ((pass == 1) ? SG_B_LO : SG_B_HI);
#pragma unroll
        for (int ks = 0; ks < 8; ++ks) {
            int kch = (ks * 16 + khalf) >> 3;
            uint32_t a[4][4];
#pragma unroll
            for (int mt = 0; mt < 4; ++mt) {
                int row = wm * 64 + mt * 16 + rbase;
                ldm4(a[mt], aBase + row * 256 +
                            ((((kch & 7) ^ (row & 7)) << 4) + ((kch & 8) << 4)));
            }
            uint32_t b[3][4];
#pragma unroll
            for (int bt = 0; bt < 3; ++bt) {
                int row = wn * 48 + bt * 16 + rbase;
                ldm4(b[bt], bBase + row * 256 +
                            ((((kch & 7) ^ (row & 7)) << 4) + ((kch & 8) << 4)));
            }
#pragma unroll
            for (int mt = 0; mt < 4; ++mt)
#pragma unroll
                for (int nt = 0; nt < 6; ++nt)
                    mma16816(acc[mt][nt], a[mt],
                             b[nt >> 1][nt & 1], b[nt >> 1][(nt & 1) + 2]);
        }
    }

    int gr = lane >> 2, gc = (lane & 3) * 2;
#pragma unroll
    for (int nt = 0; nt < 6; ++nt) {
        int col = wn * 48 + nt * 8 + gc;
        float b0 = g_bsm[col], b1 = g_bsm[col + 1];
#pragma unroll
        for (int mt = 0; mt < 4; ++mt) {
            int row = m0 + wm * 64 + mt * 16 + gr;
            float2 v0 = { acc[mt][nt][0] + b0, acc[mt][nt][1] + b1 };
            float2 v1 = { acc[mt][nt][2] + b0, acc[mt][nt][3] + b1 };
            *(float2*)&g_S[(size_t)row * 192 + col]       = v0;
            *(float2*)&g_S[(size_t)(row + 8) * 192 + col] = v1;
        }
    }
}

// ---------------- big GEMM (sync loads, bf16 split x3) ----------------
#define SA_HI 0
#define SA_LO 32768
#define SB_HI 65536
#define SB_LO 98304
#define GEMM_SMEM 131072

__global__ __launch_bounds__(256) void k_gemm_mma() {
    extern __shared__ char smem[];
    int tid = threadIdx.x;
    int warp = tid >> 5, lane = tid & 31;
    int r0 = blockIdx.x * 128;     // N (W1f rows)
    int m0 = blockIdx.y * 128;     // M (nodes)

    ld_tile_n(g_Hhi, m0, smem + SA_HI, tid, 128);
    ld_tile_n(g_Hlo, m0, smem + SA_LO, tid, 128);
    ld_tile_n(g_Whi, r0, smem + SB_HI, tid, 128);
    ld_tile_n(g_Wlo, r0, smem + SB_LO, tid, 128);
    __syncthreads();

    int wm = warp & 1, wn = warp >> 1;          // 2 x 4
    uint32_t sbase = smem_u32(smem);

    float acc[4][4][4];
#pragma unroll
    for (int mt = 0; mt < 4; ++mt)
#pragma unroll
        for (int nt = 0; nt < 4; ++nt)
#pragma unroll
            for (int i = 0; i < 4; ++i) acc[mt][nt][i] = 0.f;

    int rbase = lane & 15;
    int khalf = (lane >> 4) << 3;

#pragma unroll 1
    for (int pass = 0; pass < 3; ++pass) {
        uint32_t aBase = sbase + ((pass == 2) ? SA_LO : SA_HI);
        uint32_t bBase = sbase + ((pass == 1) ? SB_LO : SB_HI);
#pragma unroll
        for (int ks = 0; ks < 8; ++ks) {
            int kch = (ks * 16 + khalf) >> 3;
            uint32_t a[4][4];
#pragma unroll
            for (int mt = 0; mt < 4; ++mt) {
                int row = wm * 64 + mt * 16 + rbase;
                ldm4(a[mt], aBase + row * 256 +
                            ((((kch & 7) ^ (row & 7)) << 4) + ((kch & 8) << 4)));
            }
            uint32_t b[2][4];
#pragma unroll
            for (int bt = 0; bt < 2; ++bt) {
                int row = wn * 32 + bt * 16 + rbase;
                ldm4(b[bt], bBase + row * 256 +
                            ((((kch & 7) ^ (row & 7)) << 4) + ((kch & 8) << 4)));
            }
#pragma unroll
            for (int mt = 0; mt < 4; ++mt)
#pragma unroll
                for (int nt = 0; nt < 4; ++nt)
                    mma16816(acc[mt][nt], a[mt],
                             b[nt >> 1][nt & 1], b[nt >> 1][(nt & 1) + 2]);
        }
    }

    // epilogue: add bias, store fp32 to g_A
    int gr = lane >> 2, gc = (lane & 3) * 2;
#pragma unroll
    for (int nt = 0; nt < 4; ++nt) {
        int col = r0 + wn * 32 + nt * 8 + gc;
        float b0 = g_b1f[col], b1 = g_b1f[col + 1];
#pragma unroll
        for (int mt = 0; mt < 4; ++mt) {
            int row = m0 + wm * 64 + mt * 16 + gr;
            float2 v0 = { acc[mt][nt][0] + b0, acc[mt][nt][1] + b1 };
            float2 v1 = { acc[mt][nt][2] + b0, acc[mt][nt][3] + b1 };
            *(float2*)&g_A[(size_t)row * RDIM + col]       = v0;
            *(float2*)&g_A[(size_t)(row + 8) * RDIM + col] = v1;
        }
    }
}

// ---------------- counting sort of edges by src ----------------
__global__ void k_zero_hist() {
    int i = blockIdx.x * blockDim.x + threadIdx.x;
    if (i < NN) g_hist[i] = 0;
}
__global__ void k_hist(const int* __restrict__ src) {
    int e = blockIdx.x * blockDim.x + threadIdx.x;
    if (e < EE) atomicAdd(&g_hist[src[e]], 1);
}
__global__ void k_scan() {
    __shared__ int sm[1024];
    int t = threadIdx.x;
    int base = t * 8;
    int p = 0;
#pragma unroll
    for (int i = 0; i < 8; ++i) p += g_hist[base + i];
    sm[t] = p;
    __syncthreads();
    int val = p;
    for (int off = 1; off < 1024; off <<= 1) {
        int v = 0;
        if (t >= off) v = sm[t - off];
        __syncthreads();
        if (t >= off) { val += v; sm[t] = val; }
        __syncthreads();
    }
    int run = val - p;
#pragma unroll
    for (int i = 0; i < 8; ++i) {
        g_off[base + i]    = run;
        g_cursor[base + i] = run;
        run += g_hist[base + i];
    }
    if (t == 1023) g_off[NN] = run;
}
__global__ void k_scatter(const int* __restrict__ src) {
    int e = blockIdx.x * blockDim.x + threadIdx.x;
    if (e < EE) {
        int p = atomicAdd(&g_cursor[src[e]], 1);
        g_sorted[p] = e;
    }
}

// ---------------- edge kernel ----------------
__global__ __launch_bounds__(64) void k_edge(const int* __restrict__ dst,
                                             float* __restrict__ out) {
    int n = blockIdx.x;
    int beg = g_off[n], end = g_off[n + 1];
    if (beg == end) return;
    int j = threadIdx.x;
    int lane = j & 31;

    float Areg[64];
    const float* Ap = &g_A[(size_t)n * RDIM + j];
#pragma unroll
    for (int d = 0; d < 64; ++d) Areg[d] = Ap[d * 64];

    float cj = g_Call[j] + g_S[(size_t)n * 192 + 64 + j];

    for (int idx = beg; idx < end; ++idx) {
        int e = g_sorted[idx];
        int m = dst[e];
        const float* Sp = &g_S[(size_t)m * 192];
        float p2lo = Sp[lane];
        float p2hi = Sp[32 + lane];
        float acc = cj + Sp[128 + j];
#pragma unroll
        for (int d = 0; d < 32; ++d)
            acc += Areg[d] * __shfl_sync(0xffffffffu, p2lo, d);
#pragma unroll
        for (int d = 0; d < 32; ++d)
            acc += Areg[32 + d] * __shfl_sync(0xffffffffu, p2hi, d);
        out[(size_t)e * 64 + j] = fmaxf(acc, 0.f);
    }
}

// ---------------- launch ----------------
extern "C" void kernel_launch(void* const* d_in, const int* in_sizes, int n_in,
                              void* d_out, int out_size) {
    const float* h     = (const float*)d_in[0];
    const int*   src   = (const int*)  d_in[1];
    const int*   dst   = (const int*)  d_in[2];
    const float* p1w   = (const float*)d_in[3];
    const float* p1b   = (const float*)d_in[4];
    const float* p2w   = (const float*)d_in[5];
    const float* p2b   = (const float*)d_in[6];
    const float* convw = (const float*)d_in[7];
    const float* convb = (const float*)d_in[8];
    const float* e2w   = (const float*)d_in[9];
    const float* e2b   = (const float*)d_in[10];
    const float* e3w   = (const float*)d_in[11];
    const float* e3b   = (const float*)d_in[12];
    const float* gam   = (const float*)d_in[13];
    const float* bet   = (const float*)d_in[14];
    const float* mean  = (const float*)d_in[15];
    const float* var   = (const float*)d_in[16];
    float* out = (float*)d_out;

    cudaFuncSetAttribute(k_gemm_mma,  cudaFuncAttributeMaxDynamicSharedMemorySize, GEMM_SMEM);
    cudaFuncSetAttribute(k_sgemm_mma, cudaFuncAttributeMaxDynamicSharedMemorySize, SG_SMEM);

    k_fold1<<<64, 256>>>(p1w, p1b, e3w, gam, var);
    k_fold2<<<192, 128>>>(p2w, p2b, convw, e2w, gam, var);
    k_call<<<1, 64>>>(e2w, e2b, e3b, convb, gam, bet, mean, var);
    k_convert_h<<<1024, 256>>>(h);
    k_sgemm_mma<<<64, 256, SG_SMEM>>>();
    k_gemm_mma<<<dim3(RDIM / 128, NN / 128), 256, GEMM_SMEM>>>();
    k_zero_hist<<<(NN + 255) / 256, 256>>>();
    k_hist<<<(EE + 255) / 256, 256>>>(src);
    k_scan<<<1, 1024>>>();
    k_scatter<<<(EE + 255) / 256, 256>>>(src);
    k_edge<<<NN, 64>>>(dst, out);
}

// round 11
// speedup vs baseline: 1.4264x; 1.4264x over previous
#include <cuda_runtime.h>
#include <cuda_bf16.h>
#include <cstdint>

#define NN   8192
#define EE   65536
#define IND  128
#define HID  64
#define RDIM 4096   // HID*HID

// ---------------- static scratch (no allocs allowed) ----------------
__device__ float g_A[(size_t)NN * RDIM];       // A' [n][d*64 + j], BN folded (128 MB)
__device__ float g_S[NN * 192];                // per-node: p2 | qs | qd
__device__ float g_b1f[RDIM];
__device__ float g_bsm[192];
__device__ float g_Call[HID];
__device__ __nv_bfloat16 g_Hhi[(size_t)NN * IND];
__device__ __nv_bfloat16 g_Hlo[(size_t)NN * IND];
__device__ __nv_bfloat16 g_Whi[(size_t)RDIM * IND];
__device__ __nv_bfloat16 g_Wlo[(size_t)RDIM * IND];
__device__ __nv_bfloat16 g_Wsmhi[192 * IND];
__device__ __nv_bfloat16 g_Wsmlo[192 * IND];
__device__ int   g_hist[NN];
__device__ int   g_off[NN + 1];
__device__ int   g_cursor[NN];
__device__ int   g_sorted[EE];

// ---------------- helpers ----------------
__device__ __forceinline__ uint32_t smem_u32(const void* p) {
    uint32_t a;
    asm("{ .reg .u64 t; cvta.to.shared.u64 t, %1; cvt.u32.u64 %0, t; }" : "=r"(a) : "l"(p));
    return a;
}
__device__ __forceinline__ void ldm4(uint32_t* r, uint32_t addr) {
    asm volatile("ldmatrix.sync.aligned.m8n8.x4.shared.b16 {%0,%1,%2,%3}, [%4];"
                 : "=r"(r[0]), "=r"(r[1]), "=r"(r[2]), "=r"(r[3]) : "r"(addr));
}
__device__ __forceinline__ void mma16816(float* d, const uint32_t* a, uint32_t b0, uint32_t b1) {
    asm volatile(
        "mma.sync.aligned.m16n8k16.row.col.f32.bf16.bf16.f32 "
        "{%0,%1,%2,%3}, {%4,%5,%6,%7}, {%8,%9}, {%0,%1,%2,%3};"
        : "+f"(d[0]), "+f"(d[1]), "+f"(d[2]), "+f"(d[3])
        : "r"(a[0]), "r"(a[1]), "r"(a[2]), "r"(a[3]), "r"(b0), "r"(b1));
}
// sync tile load: rows of 128 bf16 (256B), 16B chunk ch swizzled (ch^row)&7
__device__ __forceinline__ void ld_tile_n(const __nv_bfloat16* __restrict__ src, int row0,
                                          char* dst, int tid, int nrows) {
    for (int idx = tid; idx < nrows * 16; idx += 256) {
        int row = idx >> 4, ch = idx & 15;
        uint4 v = *(const uint4*)(src + (size_t)(row0 + row) * IND + ch * 8);
        *(uint4*)(dst + row * 256 + ((((ch & 7) ^ (row & 7)) << 4) + ((ch & 8) << 4))) = v;
    }
}

// ---------------- fold1 v3: one block per d; esT in smem; FFMA-bound ----------------
#define FOLD1_SMEM 49920
__global__ __launch_bounds__(256) void k_fold1(const float* __restrict__ p1w,
                                               const float* __restrict__ p1b,
                                               const float* __restrict__ e3w,
                                               const float* __restrict__ gam,
                                               const float* __restrict__ var) {
    extern __shared__ float fs[];
    float* hp  = fs;             // 8192  : p1w rows (j<<6)|d, [j][k]
    float* esT = fs + 8192;      // 64*65 : e3w transposed, [j][jp] stride 65
    float* pb  = fs + 12352;     // 64
    float* ss  = fs + 12416;     // 64
    int d = blockIdx.x, tid = threadIdx.x;
    for (int idx = tid; idx < 8192; idx += 256) {
        int j = idx >> 7, k = idx & 127;
        hp[idx] = p1w[(size_t)((j << 6) | d) * IND + k];
    }
    for (int idx = tid; idx < 4096; idx += 256) {
        int jp = idx >> 6, j = idx & 63;
        esT[j * 65 + jp] = e3w[idx];
    }
    if (tid < 64) {
        pb[tid] = p1b[(tid << 6) | d];
        ss[tid] = gam[tid] * rsqrtf(var[tid] + 1e-5f);
    }
    __syncthreads();

    int kq = tid & 31, jg = tid >> 5;   // k = kq*4.., jp = jg*8..
    float acc[8][4];
#pragma unroll
    for (int jj = 0; jj < 8; ++jj)
#pragma unroll
        for (int kk = 0; kk < 4; ++kk) acc[jj][kk] = 0.f;

#pragma unroll 2
    for (int j = 0; j < 64; ++j) {
        float4 hv = *(float4*)&hp[j * 128 + kq * 4];
        const float* ej = &esT[j * 65 + jg * 8];
#pragma unroll
        for (int jj = 0; jj < 8; ++jj) {
            float e = ej[jj];
            acc[jj][0] += e * hv.x;
            acc[jj][1] += e * hv.y;
            acc[jj][2] += e * hv.z;
            acc[jj][3] += e * hv.w;
        }
    }
#pragma unroll
    for (int jj = 0; jj < 8; ++jj) {
        int jp = jg * 8 + jj;
        float s = ss[jp];
        size_t ro = (size_t)((d << 6) | jp) * IND + kq * 4;
#pragma unroll
        for (int kk = 0; kk < 4; ++kk) {
            float v = s * acc[jj][kk];
            __nv_bfloat16 hi = __float2bfloat16(v);
            g_Whi[ro + kk] = hi;
            g_Wlo[ro + kk] = __float2bfloat16(v - __bfloat162float(hi));
        }
    }
    if (tid < 64) {
        float b = 0.f;
        for (int j = 0; j < 64; ++j) b += esT[j * 65 + tid] * pb[j];
        g_b1f[(d << 6) | tid] = ss[tid] * b;
    }
}

// ---------------- fold2 (+ hist zero + Call fold) ----------------
__global__ void k_fold2(const float* __restrict__ p2w, const float* __restrict__ p2b,
                        const float* __restrict__ convw, const float* __restrict__ e2w,
                        const float* __restrict__ gam, const float* __restrict__ var,
                        const float* __restrict__ e2b, const float* __restrict__ e3b,
                        const float* __restrict__ convb, const float* __restrict__ bet,
                        const float* __restrict__ mean) {
    int c = blockIdx.x;            // 0..191
    int k = threadIdx.x;           // 0..127
    // zero edge histogram (192*128 = 24576 >= NN)
    int gi = c * 128 + k;
    if (gi < NN) g_hist[gi] = 0;

    float val;
    if (c < 64) {
        val = p2w[c * IND + k];
        if (k == 0) g_bsm[c] = p2b[c];
    } else {
        int j  = (c - 64) & 63;
        int cc = (c >= 128) ? 1 : 0;
        float s = gam[j] * rsqrtf(var[j] + 1e-5f);
        float a = 0.f;
#pragma unroll
        for (int u = 0; u < 3; ++u) {
            int i = k - u + 1;
            if (i >= 0 && i < IND) a += convw[cc * 3 + u] * e2w[j * IND + i];
        }
        val = s * a;
        if (k == 0) g_bsm[c] = 0.f;
    }
    __nv_bfloat16 hi = __float2bfloat16(val);
    g_Wsmhi[c * IND + k] = hi;
    g_Wsmlo[c * IND + k] = __float2bfloat16(val - __bfloat162float(hi));

    // Call fold (block 0, 64 threads)
    if (c == 0 && k < 64) {
        float s = gam[k] * rsqrtf(var[k] + 1e-5f);
        float t = bet[k] - mean[k] * s;
        float rs = 0.f;
        for (int i = 0; i < IND; ++i) rs += e2w[k * IND + i];
        g_Call[k] = s * (convb[0] * rs + e2b[k] + e3b[k]) + t;
    }
}

// ---------------- bf16 split of h (+ edge histogram) ----------------
__global__ void k_convert_h(const float* __restrict__ h, const int* __restrict__ src) {
    int i = blockIdx.x * 256 + threadIdx.x;   // 262144 threads, x4 elems
    float4 v = ((const float4*)h)[i];
    __nv_bfloat16 h0 = __float2bfloat16(v.x), h1 = __float2bfloat16(v.y);
    __nv_bfloat16 h2 = __float2bfloat16(v.z), h3 = __float2bfloat16(v.w);
    __nv_bfloat162* Hh = (__nv_bfloat162*)g_Hhi;
    __nv_bfloat162* Hl = (__nv_bfloat162*)g_Hlo;
    Hh[2 * i]     = __nv_bfloat162(h0, h1);
    Hh[2 * i + 1] = __nv_bfloat162(h2, h3);
    Hl[2 * i]     = __nv_bfloat162(__float2bfloat16(v.x - __bfloat162float(h0)),
                                   __float2bfloat16(v.y - __bfloat162float(h1)));
    Hl[2 * i + 1] = __nv_bfloat162(__float2bfloat16(v.z - __bfloat162float(h2)),
                                   __float2bfloat16(v.w - __bfloat162float(h3)));
    if (i < EE) atomicAdd(&g_hist[src[i]], 1);
}

// ---------------- shared GEMM mainloop pass ----------------
__device__ __forceinline__ void gemm_pass(uint32_t aBase, uint32_t bBase,
                                          int wm, int wn, int rbase, int khalf,
                                          float (*acc)[4][4]) {
#pragma unroll
    for (int ks = 0; ks < 8; ++ks) {
        int kch = (ks * 16 + khalf) >> 3;
        uint32_t a[4][4];
#pragma unroll
        for (int mt = 0; mt < 4; ++mt) {
            int row = wm * 64 + mt * 16 + rbase;
            ldm4(a[mt], aBase + row * 256 +
                        ((((kch & 7) ^ (row & 7)) << 4) + ((kch & 8) << 4)));
        }
        uint32_t b[2][4];
#pragma unroll
        for (int bt = 0; bt < 2; ++bt) {
            int row = wn * 32 + bt * 16 + rbase;
            ldm4(b[bt], bBase + row * 256 +
                        ((((kch & 7) ^ (row & 7)) << 4) + ((kch & 8) << 4)));
        }
#pragma unroll
        for (int mt = 0; mt < 4; ++mt)
#pragma unroll
            for (int nt = 0; nt < 4; ++nt)
                mma16816(acc[mt][nt], a[mt],
                         b[nt >> 1][nt & 1], b[nt >> 1][(nt & 1) + 2]);
    }
}

// ---------------- small GEMM on tensor cores: S = h @ Wsm^T + bias ----------------
#define SG_A_HI 0
#define SG_A_LO 32768
#define SG_B_HI 65536
#define SG_B_LO 114688
#define SG_SMEM 163840

__global__ __launch_bounds__(256) void k_sgemm_mma() {
    extern __shared__ char smem[];
    int tid = threadIdx.x;
    int warp = tid >> 5, lane = tid & 31;
    int m0 = blockIdx.x * 128;

    ld_tile_n(g_Hhi,   m0, smem + SG_A_HI, tid, 128);
    ld_tile_n(g_Hlo,   m0, smem + SG_A_LO, tid, 128);
    ld_tile_n(g_Wsmhi, 0,  smem + SG_B_HI, tid, 192);
    ld_tile_n(g_Wsmlo, 0,  smem + SG_B_LO, tid, 192);
    __syncthreads();

    int wm = warp & 1, wn = warp >> 1;   // 2 x 4
    uint32_t sbase = smem_u32(smem);
    float acc[4][6][4];
#pragma unroll
    for (int mt = 0; mt < 4; ++mt)
#pragma unroll
        for (int nt = 0; nt < 6; ++nt)
#pragma unroll
            for (int i = 0; i < 4; ++i) acc[mt][nt][i] = 0.f;

    int rbase = lane & 15;
    int khalf = (lane >> 4) << 3;

#pragma unroll 1
    for (int pass = 0; pass < 3; ++pass) {
        uint32_t aBase = sbase + ((pass == 2) ? SG_A_LO : SG_A_HI);
        uint32_t bBase = sbase + ((pass == 1) ? SG_B_LO : SG_B_HI);
#pragma unroll
        for (int ks = 0; ks < 8; ++ks) {
            int kch = (ks * 16 + khalf) >> 3;
            uint32_t a[4][4];
#pragma unroll
            for (int mt = 0; mt < 4; ++mt) {
                int row = wm * 64 + mt * 16 + rbase;
                ldm4(a[mt], aBase + row * 256 +
                            ((((kch & 7) ^ (row & 7)) << 4) + ((kch & 8) << 4)));
            }
            uint32_t b[3][4];
#pragma unroll
            for (int bt = 0; bt < 3; ++bt) {
                int row = wn * 48 + bt * 16 + rbase;
                ldm4(b[bt], bBase + row * 256 +
                            ((((kch & 7) ^ (row & 7)) << 4) + ((kch & 8) << 4)));
            }
#pragma unroll
            for (int mt = 0; mt < 4; ++mt)
#pragma unroll
                for (int nt = 0; nt < 6; ++nt)
                    mma16816(acc[mt][nt], a[mt],
                             b[nt >> 1][nt & 1], b[nt >> 1][(nt & 1) + 2]);
        }
    }

    int gr = lane >> 2, gc = (lane & 3) * 2;
#pragma unroll
    for (int nt = 0; nt < 6; ++nt) {
        int col = wn * 48 + nt * 8 + gc;
        float b0 = g_bsm[col], b1 = g_bsm[col + 1];
#pragma unroll
        for (int mt = 0; mt < 4; ++mt) {
            int row = m0 + wm * 64 + mt * 16 + gr;
            float2 v0 = { acc[mt][nt][0] + b0, acc[mt][nt][1] + b1 };
            float2 v1 = { acc[mt][nt][2] + b0, acc[mt][nt][3] + b1 };
            *(float2*)&g_S[(size_t)row * 192 + col]       = v0;
            *(float2*)&g_S[(size_t)(row + 8) * 192 + col] = v1;
        }
    }
}

// ---------------- big GEMM (register-staged lo tiles, bf16 split x3) ----------------
#define SA_HI 0
#define SA_LO 32768
#define SB_HI 65536
#define SB_LO 98304
#define GEMM_SMEM 131072

__global__ __launch_bounds__(256) void k_gemm_mma() {
    extern __shared__ char smem[];
    int tid = threadIdx.x;
    int warp = tid >> 5, lane = tid & 31;
    int r0 = blockIdx.x * 128;     // N (W1f rows)
    int m0 = blockIdx.y * 128;     // M (nodes)

    // hi tiles -> smem (sync)
    ld_tile_n(g_Hhi, m0, smem + SA_HI, tid, 128);
    ld_tile_n(g_Whi, r0, smem + SB_HI, tid, 128);
    // lo tiles -> registers (LDG latency hides under pass 0)
    uint4 stA[8], stB[8];
#pragma unroll
    for (int i = 0; i < 8; ++i) {
        int idx = tid + i * 256;
        int row = idx >> 4, ch = idx & 15;
        stA[i] = *(const uint4*)(g_Hlo + (size_t)(m0 + row) * IND + ch * 8);
        stB[i] = *(const uint4*)(g_Wlo + (size_t)(r0 + row) * IND + ch * 8);
    }
    __syncthreads();

    int wm = warp & 1, wn = warp >> 1;          // 2 x 4
    uint32_t sbase = smem_u32(smem);
    float acc[4][4][4];
#pragma unroll
    for (int mt = 0; mt < 4; ++mt)
#pragma unroll
        for (int nt = 0; nt < 4; ++nt)
#pragma unroll
            for (int i = 0; i < 4; ++i) acc[mt][nt][i] = 0.f;

    int rbase = lane & 15;
    int khalf = (lane >> 4) << 3;

    // pass 0: hi x hi
    gemm_pass(sbase + SA_HI, sbase + SB_HI, wm, wn, rbase, khalf, acc);

    // commit staged lo tiles to smem
#pragma unroll
    for (int i = 0; i < 8; ++i) {
        int idx = tid + i * 256;
        int row = idx >> 4, ch = idx & 15;
        uint32_t off = row * 256 + ((((ch & 7) ^ (row & 7)) << 4) + ((ch & 8) << 4));
        *(uint4*)(smem + SA_LO + off) = stA[i];
        *(uint4*)(smem + SB_LO + off) = stB[i];
    }
    __syncthreads();

    // pass 1: hi x lo, pass 2: lo x hi
    gemm_pass(sbase + SA_HI, sbase + SB_LO, wm, wn, rbase, khalf, acc);
    gemm_pass(sbase + SA_LO, sbase + SB_HI, wm, wn, rbase, khalf, acc);

    // epilogue: add bias, store fp32 to g_A
    int gr = lane >> 2, gc = (lane & 3) * 2;
#pragma unroll
    for (int nt = 0; nt < 4; ++nt) {
        int col = r0 + wn * 32 + nt * 8 + gc;
        float b0 = g_b1f[col], b1 = g_b1f[col + 1];
#pragma unroll
        for (int mt = 0; mt < 4; ++mt) {
            int row = m0 + wm * 64 + mt * 16 + gr;
            float2 v0 = { acc[mt][nt][0] + b0, acc[mt][nt][1] + b1 };
            float2 v1 = { acc[mt][nt][2] + b0, acc[mt][nt][3] + b1 };
            *(float2*)&g_A[(size_t)row * RDIM + col]       = v0;
            *(float2*)&g_A[(size_t)(row + 8) * RDIM + col] = v1;
        }
    }
}

// ---------------- counting sort: scan + scatter ----------------
__global__ void k_scan() {
    __shared__ int sm[1024];
    int t = threadIdx.x;
    int base = t * 8;
    int p = 0;
#pragma unroll
    for (int i = 0; i < 8; ++i) p += g_hist[base + i];
    sm[t] = p;
    __syncthreads();
    int val = p;
    for (int off = 1; off < 1024; off <<= 1) {
        int v = 0;
        if (t >= off) v = sm[t - off];
        __syncthreads();
        if (t >= off) { val += v; sm[t] = val; }
        __syncthreads();
    }
    int run = val - p;
#pragma unroll
    for (int i = 0; i < 8; ++i) {
        g_off[base + i]    = run;
        g_cursor[base + i] = run;
        run += g_hist[base + i];
    }
    if (t == 1023) g_off[NN] = run;
}
__global__ void k_scatter(const int* __restrict__ src) {
    int e = blockIdx.x * blockDim.x + threadIdx.x;
    if (e < EE) {
        int p = atomicAdd(&g_cursor[src[e]], 1);
        g_sorted[p] = e;
    }
}

// ---------------- edge kernel ----------------
__global__ __launch_bounds__(64) void k_edge(const int* __restrict__ dst,
                                             float* __restrict__ out) {
    int n = blockIdx.x;
    int beg = g_off[n], end = g_off[n + 1];
    if (beg == end) return;
    int j = threadIdx.x;
    int lane = j & 31;

    float Areg[64];
    const float* Ap = &g_A[(size_t)n * RDIM + j];
#pragma unroll
    for (int d = 0; d < 64; ++d) Areg[d] = Ap[d * 64];

    float cj = g_Call[j] + g_S[(size_t)n * 192 + 64 + j];

    for (int idx = beg; idx < end; ++idx) {
        int e = g_sorted[idx];
        int m = dst[e];
        const float* Sp = &g_S[(size_t)m * 192];
        float p2lo = Sp[lane];
        float p2hi = Sp[32 + lane];
        float acc = cj + Sp[128 + j];
#pragma unroll
        for (int d = 0; d < 32; ++d)
            acc += Areg[d] * __shfl_sync(0xffffffffu, p2lo, d);
#pragma unroll
        for (int d = 0; d < 32; ++d)
            acc += Areg[32 + d] * __shfl_sync(0xffffffffu, p2hi, d);
        out[(size_t)e * 64 + j] = fmaxf(acc, 0.f);
    }
}

// ---------------- launch ----------------
extern "C" void kernel_launch(void* const* d_in, const int* in_sizes, int n_in,
                              void* d_out, int out_size) {
    const float* h     = (const float*)d_in[0];
    const int*   src   = (const int*)  d_in[1];
    const int*   dst   = (const int*)  d_in[2];
    const float* p1w   = (const float*)d_in[3];
    const float* p1b   = (const float*)d_in[4];
    const float* p2w   = (const float*)d_in[5];
    const float* p2b   = (const float*)d_in[6];
    const float* convw = (const float*)d_in[7];
    const float* convb = (const float*)d_in[8];
    const float* e2w   = (const float*)d_in[9];
    const float* e2b   = (const float*)d_in[10];
    const float* e3w   = (const float*)d_in[11];
    const float* e3b   = (const float*)d_in[12];
    const float* gam   = (const float*)d_in[13];
    const float* bet   = (const float*)d_in[14];
    const float* mean  = (const float*)d_in[15];
    const float* var   = (const float*)d_in[16];
    float* out = (float*)d_out;

    cudaFuncSetAttribute(k_fold1,     cudaFuncAttributeMaxDynamicSharedMemorySize, FOLD1_SMEM);
    cudaFuncSetAttribute(k_gemm_mma,  cudaFuncAttributeMaxDynamicSharedMemorySize, GEMM_SMEM);
    cudaFuncSetAttribute(k_sgemm_mma, cudaFuncAttributeMaxDynamicSharedMemorySize, SG_SMEM);

    k_fold1<<<64, 256, FOLD1_SMEM>>>(p1w, p1b, e3w, gam, var);
    k_fold2<<<192, 128>>>(p2w, p2b, convw, e2w, gam, var, e2b, e3b, convb, bet, mean);
    k_convert_h<<<1024, 256>>>(h, src);
    k_sgemm_mma<<<64, 256, SG_SMEM>>>();
    k_gemm_mma<<<dim3(RDIM / 128, NN / 128), 256, GEMM_SMEM>>>();
    k_scan<<<1, 1024>>>();
    k_scatter<<<(EE + 255) / 256, 256>>>(src);
    k_edge<<<NN, 64>>>(dst, out);
}

// round 12
// speedup vs baseline: 1.4900x; 1.0446x over previous
#include <cuda_runtime.h>
#include <cuda_fp16.h>
#include <cstdint>

#define NN   8192
#define EE   65536
#define IND  128
#define HID  64
#define RDIM 4096   // HID*HID

// ---------------- static scratch (no allocs allowed) ----------------
__device__ float g_A[(size_t)NN * RDIM];       // A' [n][d*64 + j], BN folded (128 MB)
__device__ float g_S[NN * 192];                // per-node: p2 | qs | qd
__device__ float g_b1f[RDIM];
__device__ float g_bsm[192];
__device__ float g_Call[HID];
__device__ __half g_Hhi[(size_t)NN * IND];
__device__ __half g_Hlo[(size_t)NN * IND];
__device__ __half g_Whi[(size_t)RDIM * IND];
__device__ __half g_Wsmhi[192 * IND];
__device__ __half g_Wsmlo[192 * IND];
__device__ int   g_hist[NN];
__device__ int   g_off[NN + 1];
__device__ int   g_cursor[NN];
__device__ int   g_sorted[EE];

// ---------------- helpers ----------------
__device__ __forceinline__ uint32_t smem_u32(const void* p) {
    uint32_t a;
    asm("{ .reg .u64 t; cvta.to.shared.u64 t, %1; cvt.u32.u64 %0, t; }" : "=r"(a) : "l"(p));
    return a;
}
__device__ __forceinline__ void ldm4(uint32_t* r, uint32_t addr) {
    asm volatile("ldmatrix.sync.aligned.m8n8.x4.shared.b16 {%0,%1,%2,%3}, [%4];"
                 : "=r"(r[0]), "=r"(r[1]), "=r"(r[2]), "=r"(r[3]) : "r"(addr));
}
__device__ __forceinline__ void mma16816(float* d, const uint32_t* a, uint32_t b0, uint32_t b1) {
    asm volatile(
        "mma.sync.aligned.m16n8k16.row.col.f32.f16.f16.f32 "
        "{%0,%1,%2,%3}, {%4,%5,%6,%7}, {%8,%9}, {%0,%1,%2,%3};"
        : "+f"(d[0]), "+f"(d[1]), "+f"(d[2]), "+f"(d[3])
        : "r"(a[0]), "r"(a[1]), "r"(a[2]), "r"(a[3]), "r"(b0), "r"(b1));
}
// sync tile load: rows of 128 fp16 (256B), 16B chunk ch swizzled (ch^row)&7
__device__ __forceinline__ void ld_tile_n(const __half* __restrict__ src, int row0,
                                          char* dst, int tid, int nrows) {
    for (int idx = tid; idx < nrows * 16; idx += 256) {
        int row = idx >> 4, ch = idx & 15;
        uint4 v = *(const uint4*)(src + (size_t)(row0 + row) * IND + ch * 8);
        *(uint4*)(dst + row * 256 + ((((ch & 7) ^ (row & 7)) << 4) + ((ch & 8) << 4))) = v;
    }
}

// ---------------- fold1 v3: one block per d; esT in smem; writes fp16 Whi + b1f ------
#define FOLD1_SMEM 49920
__global__ __launch_bounds__(256) void k_fold1(const float* __restrict__ p1w,
                                               const float* __restrict__ p1b,
                                               const float* __restrict__ e3w,
                                               const float* __restrict__ gam,
                                               const float* __restrict__ var) {
    extern __shared__ float fs[];
    float* hp  = fs;             // 8192  : p1w rows (j<<6)|d, [j][k]
    float* esT = fs + 8192;      // 64*65 : e3w transposed, [j][jp] stride 65
    float* pb  = fs + 12352;     // 64
    float* ss  = fs + 12416;     // 64
    int d = blockIdx.x, tid = threadIdx.x;
    for (int idx = tid; idx < 8192; idx += 256) {
        int j = idx >> 7, k = idx & 127;
        hp[idx] = p1w[(size_t)((j << 6) | d) * IND + k];
    }
    for (int idx = tid; idx < 4096; idx += 256) {
        int jp = idx >> 6, j = idx & 63;
        esT[j * 65 + jp] = e3w[idx];
    }
    if (tid < 64) {
        pb[tid] = p1b[(tid << 6) | d];
        ss[tid] = gam[tid] * rsqrtf(var[tid] + 1e-5f);
    }
    __syncthreads();

    int kq = tid & 31, jg = tid >> 5;   // k = kq*4.., jp = jg*8..
    float acc[8][4];
#pragma unroll
    for (int jj = 0; jj < 8; ++jj)
#pragma unroll
        for (int kk = 0; kk < 4; ++kk) acc[jj][kk] = 0.f;

#pragma unroll 2
    for (int j = 0; j < 64; ++j) {
        float4 hv = *(float4*)&hp[j * 128 + kq * 4];
        const float* ej = &esT[j * 65 + jg * 8];
#pragma unroll
        for (int jj = 0; jj < 8; ++jj) {
            float e = ej[jj];
            acc[jj][0] += e * hv.x;
            acc[jj][1] += e * hv.y;
            acc[jj][2] += e * hv.z;
            acc[jj][3] += e * hv.w;
        }
    }
#pragma unroll
    for (int jj = 0; jj < 8; ++jj) {
        int jp = jg * 8 + jj;
        float s = ss[jp];
        size_t ro = (size_t)((d << 6) | jp) * IND + kq * 4;
#pragma unroll
        for (int kk = 0; kk < 4; ++kk)
            g_Whi[ro + kk] = __float2half(s * acc[jj][kk]);
    }
    if (tid < 64) {
        float b = 0.f;
        for (int j = 0; j < 64; ++j) b += esT[j * 65 + tid] * pb[j];
        g_b1f[(d << 6) | tid] = ss[tid] * b;
    }
}

// ---------------- fold2 (+ hist zero + Call fold), fp16 split small weights ----------
__global__ void k_fold2(const float* __restrict__ p2w, const float* __restrict__ p2b,
                        const float* __restrict__ convw, const float* __restrict__ e2w,
                        const float* __restrict__ gam, const float* __restrict__ var,
                        const float* __restrict__ e2b, const float* __restrict__ e3b,
                        const float* __restrict__ convb, const float* __restrict__ bet,
                        const float* __restrict__ mean) {
    int c = blockIdx.x;            // 0..191
    int k = threadIdx.x;           // 0..127
    int gi = c * 128 + k;
    if (gi < NN) g_hist[gi] = 0;

    float val;
    if (c < 64) {
        val = p2w[c * IND + k];
        if (k == 0) g_bsm[c] = p2b[c];
    } else {
        int j  = (c - 64) & 63;
        int cc = (c >= 128) ? 1 : 0;
        float s = gam[j] * rsqrtf(var[j] + 1e-5f);
        float a = 0.f;
#pragma unroll
        for (int u = 0; u < 3; ++u) {
            int i = k - u + 1;
            if (i >= 0 && i < IND) a += convw[cc * 3 + u] * e2w[j * IND + i];
        }
        val = s * a;
        if (k == 0) g_bsm[c] = 0.f;
    }
    __half hi = __float2half(val);
    g_Wsmhi[c * IND + k] = hi;
    g_Wsmlo[c * IND + k] = __float2half(val - __half2float(hi));

    if (c == 0 && k < 64) {
        float s = gam[k] * rsqrtf(var[k] + 1e-5f);
        float t = bet[k] - mean[k] * s;
        float rs = 0.f;
        for (int i = 0; i < IND; ++i) rs += e2w[k * IND + i];
        g_Call[k] = s * (convb[0] * rs + e2b[k] + e3b[k]) + t;
    }
}

// ---------------- fp16 split of h (+ edge histogram) ----------------
__global__ void k_convert_h(const float* __restrict__ h, const int* __restrict__ src) {
    int i = blockIdx.x * 256 + threadIdx.x;   // 262144 threads, x4 elems
    float4 v = ((const float4*)h)[i];
    __half h0 = __float2half(v.x), h1 = __float2half(v.y);
    __half h2 = __float2half(v.z), h3 = __float2half(v.w);
    __half2* Hh = (__half2*)g_Hhi;
    __half2* Hl = (__half2*)g_Hlo;
    Hh[2 * i]     = __half2(h0, h1);
    Hh[2 * i + 1] = __half2(h2, h3);
    Hl[2 * i]     = __half2(__float2half(v.x - __half2float(h0)),
                            __float2half(v.y - __half2float(h1)));
    Hl[2 * i + 1] = __half2(__float2half(v.z - __half2float(h2)),
                            __float2half(v.w - __half2float(h3)));
    if (i < EE) atomicAdd(&g_hist[src[i]], 1);
}

// ---------------- shared GEMM mainloop pass (warp tile 64x32, 2x4 warps) -------------
__device__ __forceinline__ void gemm_pass(uint32_t aBase, uint32_t bBase,
                                          int wm, int wn, int rbase, int khalf,
                                          float (*acc)[4][4]) {
#pragma unroll
    for (int ks = 0; ks < 8; ++ks) {
        int kch = (ks * 16 + khalf) >> 3;
        uint32_t a[4][4];
#pragma unroll
        for (int mt = 0; mt < 4; ++mt) {
            int row = wm * 64 + mt * 16 + rbase;
            ldm4(a[mt], aBase + row * 256 +
                        ((((kch & 7) ^ (row & 7)) << 4) + ((kch & 8) << 4)));
        }
        uint32_t b[2][4];
#pragma unroll
        for (int bt = 0; bt < 2; ++bt) {
            int row = wn * 32 + bt * 16 + rbase;
            ldm4(b[bt], bBase + row * 256 +
                        ((((kch & 7) ^ (row & 7)) << 4) + ((kch & 8) << 4)));
        }
#pragma unroll
        for (int mt = 0; mt < 4; ++mt)
#pragma unroll
            for (int nt = 0; nt < 4; ++nt)
                mma16816(acc[mt][nt], a[mt],
                         b[nt >> 1][nt & 1], b[nt >> 1][(nt & 1) + 2]);
    }
}

// ---------------- fused GEMM kernel ----------------
// bid < 64   : small GEMM tile (M=128 of S = h@Wsm^T+bias), fp16 3-pass
// bid >= 64  : big GEMM tile 128x128 (A' = h@W1f^T+b1f),    fp16 2-pass
#define FU_A_HI 0
#define FU_A_LO 32768
#define FU_B_HI 65536
#define FU_B_LO 114688
#define FU_SMEM 163840

__global__ __launch_bounds__(256) void k_gemm_fused() {
    extern __shared__ char smem[];
    int bid = blockIdx.x;
    int tid = threadIdx.x;
    int warp = tid >> 5, lane = tid & 31;
    uint32_t sbase = smem_u32(smem);
    int rbase = lane & 15;
    int khalf = (lane >> 4) << 3;

    if (bid >= 64) {
        // ---- big GEMM ----
        int g  = bid - 64;
        int r0 = (g & 31) * 128;     // N (W1f rows)
        int m0 = (g >> 5) * 128;     // M (nodes)

        ld_tile_n(g_Hhi, m0, smem + FU_A_HI, tid, 128);
        ld_tile_n(g_Hlo, m0, smem + FU_A_LO, tid, 128);
        ld_tile_n(g_Whi, r0, smem + FU_B_HI, tid, 128);
        __syncthreads();

        int wm = warp & 1, wn = warp >> 1;          // 2 x 4
        float acc[4][4][4];
#pragma unroll
        for (int mt = 0; mt < 4; ++mt)
#pragma unroll
            for (int nt = 0; nt < 4; ++nt)
#pragma unroll
                for (int i = 0; i < 4; ++i) acc[mt][nt][i] = 0.f;

        gemm_pass(sbase + FU_A_HI, sbase + FU_B_HI, wm, wn, rbase, khalf, acc);
        gemm_pass(sbase + FU_A_LO, sbase + FU_B_HI, wm, wn, rbase, khalf, acc);

        int gr = lane >> 2, gc = (lane & 3) * 2;
#pragma unroll
        for (int nt = 0; nt < 4; ++nt) {
            int col = r0 + wn * 32 + nt * 8 + gc;
            float b0 = g_b1f[col], b1 = g_b1f[col + 1];
#pragma unroll
            for (int mt = 0; mt < 4; ++mt) {
                int row = m0 + wm * 64 + mt * 16 + gr;
                float2 v0 = { acc[mt][nt][0] + b0, acc[mt][nt][1] + b1 };
                float2 v1 = { acc[mt][nt][2] + b0, acc[mt][nt][3] + b1 };
                *(float2*)&g_A[(size_t)row * RDIM + col]       = v0;
                *(float2*)&g_A[(size_t)(row + 8) * RDIM + col] = v1;
            }
        }
    } else {
        // ---- small GEMM: S tile (M=128 x N=192), 3 passes ----
        int m0 = bid * 128;
        ld_tile_n(g_Hhi,   m0, smem + FU_A_HI, tid, 128);
        ld_tile_n(g_Hlo,   m0, smem + FU_A_LO, tid, 128);
        ld_tile_n(g_Wsmhi, 0,  smem + FU_B_HI, tid, 192);
        ld_tile_n(g_Wsmlo, 0,  smem + FU_B_LO, tid, 192);
        __syncthreads();

        int wm = warp & 1, wn = warp >> 1;   // 2 x 4, warp tile 64x48
        float acc[4][6][4];
#pragma unroll
        for (int mt = 0; mt < 4; ++mt)
#pragma unroll
            for (int nt = 0; nt < 6; ++nt)
#pragma unroll
                for (int i = 0; i < 4; ++i) acc[mt][nt][i] = 0.f;

#pragma unroll 1
        for (int pass = 0; pass < 3; ++pass) {
            uint32_t aBase = sbase + ((pass == 2) ? FU_A_LO : FU_A_HI);
            uint32_t bBase = sbase + ((pass == 1) ? FU_B_LO : FU_B_HI);
#pragma unroll
            for (int ks = 0; ks < 8; ++ks) {
                int kch = (ks * 16 + khalf) >> 3;
                uint32_t a[4][4];
#pragma unroll
                for (int mt = 0; mt < 4; ++mt) {
                    int row = wm * 64 + mt * 16 + rbase;
                    ldm4(a[mt], aBase + row * 256 +
                                ((((kch & 7) ^ (row & 7)) << 4) + ((kch & 8) << 4)));
                }
                uint32_t b[3][4];
#pragma unroll
                for (int bt = 0; bt < 3; ++bt) {
                    int row = wn * 48 + bt * 16 + rbase;
                    ldm4(b[bt], bBase + row * 256 +
                                ((((kch & 7) ^ (row & 7)) << 4) + ((kch & 8) << 4)));
                }
#pragma unroll
                for (int mt = 0; mt < 4; ++mt)
#pragma unroll
                    for (int nt = 0; nt < 6; ++nt)
                        mma16816(acc[mt][nt], a[mt],
                                 b[nt >> 1][nt & 1], b[nt >> 1][(nt & 1) + 2]);
            }
        }

        int gr = lane >> 2, gc = (lane & 3) * 2;
#pragma unroll
        for (int nt = 0; nt < 6; ++nt) {
            int col = wn * 48 + nt * 8 + gc;
            float b0 = g_bsm[col], b1 = g_bsm[col + 1];
#pragma unroll
            for (int mt = 0; mt < 4; ++mt) {
                int row = m0 + wm * 64 + mt * 16 + gr;
                float2 v0 = { acc[mt][nt][0] + b0, acc[mt][nt][1] + b1 };
                float2 v1 = { acc[mt][nt][2] + b0, acc[mt][nt][3] + b1 };
                *(float2*)&g_S[(size_t)row * 192 + col]       = v0;
                *(float2*)&g_S[(size_t)(row + 8) * 192 + col] = v1;
            }
        }
    }
}

// ---------------- counting sort: scan + scatter ----------------
__global__ void k_scan() {
    __shared__ int sm[1024];
    int t = threadIdx.x;
    int base = t * 8;
    int p = 0;
#pragma unroll
    for (int i = 0; i < 8; ++i) p += g_hist[base + i];
    sm[t] = p;
    __syncthreads();
    int val = p;
    for (int off = 1; off < 1024; off <<= 1) {
        int v = 0;
        if (t >= off) v = sm[t - off];
        __syncthreads();
        if (t >= off) { val += v; sm[t] = val; }
        __syncthreads();
    }
    int run = val - p;
#pragma unroll
    for (int i = 0; i < 8; ++i) {
        g_off[base + i]    = run;
        g_cursor[base + i] = run;
        run += g_hist[base + i];
    }
    if (t == 1023) g_off[NN] = run;
}
__global__ void k_scatter(const int* __restrict__ src) {
    int e = blockIdx.x * blockDim.x + threadIdx.x;
    if (e < EE) {
        int p = atomicAdd(&g_cursor[src[e]], 1);
        g_sorted[p] = e;
    }
}

// ---------------- edge kernel ----------------
__global__ __launch_bounds__(64) void k_edge(const int* __restrict__ dst,
                                             float* __restrict__ out) {
    int n = blockIdx.x;
    int beg = g_off[n], end = g_off[n + 1];
    if (beg == end) return;
    int j = threadIdx.x;
    int lane = j & 31;

    float Areg[64];
    const float* Ap = &g_A[(size_t)n * RDIM + j];
#pragma unroll
    for (int d = 0; d < 64; ++d) Areg[d] = Ap[d * 64];

    float cj = g_Call[j] + g_S[(size_t)n * 192 + 64 + j];

    for (int idx = beg; idx < end; ++idx) {
        int e = g_sorted[idx];
        int m = dst[e];
        const float* Sp = &g_S[(size_t)m * 192];
        float p2lo = Sp[lane];
        float p2hi = Sp[32 + lane];
        float acc = cj + Sp[128 + j];
#pragma unroll
        for (int d = 0; d < 32; ++d)
            acc += Areg[d] * __shfl_sync(0xffffffffu, p2lo, d);
#pragma unroll
        for (int d = 0; d < 32; ++d)
            acc += Areg[32 + d] * __shfl_sync(0xffffffffu, p2hi, d);
        out[(size_t)e * 64 + j] = fmaxf(acc, 0.f);
    }
}

// ---------------- launch ----------------
extern "C" void kernel_launch(void* const* d_in, const int* in_sizes, int n_in,
                              void* d_out, int out_size) {
    const float* h     = (const float*)d_in[0];
    const int*   src   = (const int*)  d_in[1];
    const int*   dst   = (const int*)  d_in[2];
    const float* p1w   = (const float*)d_in[3];
    const float* p1b   = (const float*)d_in[4];
    const float* p2w   = (const float*)d_in[5];
    const float* p2b   = (const float*)d_in[6];
    const float* convw = (const float*)d_in[7];
    const float* convb = (const float*)d_in[8];
    const float* e2w   = (const float*)d_in[9];
    const float* e2b   = (const float*)d_in[10];
    const float* e3w   = (const float*)d_in[11];
    const float* e3b   = (const float*)d_in[12];
    const float* gam   = (const float*)d_in[13];
    const float* bet   = (const float*)d_in[14];
    const float* mean  = (const float*)d_in[15];
    const float* var   = (const float*)d_in[16];
    float* out = (float*)d_out;

    cudaFuncSetAttribute(k_fold1,      cudaFuncAttributeMaxDynamicSharedMemorySize, FOLD1_SMEM);
    cudaFuncSetAttribute(k_gemm_fused, cudaFuncAttributeMaxDynamicSharedMemorySize, FU_SMEM);

    k_fold1<<<64, 256, FOLD1_SMEM>>>(p1w, p1b, e3w, gam, var);
    k_fold2<<<192, 128>>>(p2w, p2b, convw, e2w, gam, var, e2b, e3b, convb, bet, mean);
    k_convert_h<<<1024, 256>>>(h, src);
    k_scan<<<1, 1024>>>();
    k_scatter<<<(EE + 255) / 256, 256>>>(src);
    k_gemm_fused<<<64 + NN / 128 * (RDIM / 128), 256, FU_SMEM>>>();
    k_edge<<<NN, 64>>>(dst, out);
}

// round 13
// speedup vs baseline: 1.7923x; 1.2029x over previous
#include <cuda_runtime.h>
#include <cuda_fp16.h>
#include <cstdint>

#define NN   8192
#define EE   65536
#define IND  128
#define HID  64
#define RDIM 4096   // HID*HID

// ---------------- static scratch (no allocs allowed) ----------------
__device__ float g_A[(size_t)NN * RDIM];       // A' [n][d*64 + j], BN folded (128 MB)
__device__ float g_S[NN * 192];                // per-node: p2 | qs | qd
__device__ float g_b1f[RDIM];
__device__ float g_bsm[192];
__device__ float g_Call[HID];
__device__ __half g_Hhi[(size_t)NN * IND];
__device__ __half g_Hlo[(size_t)NN * IND];
__device__ __half g_Whi[(size_t)RDIM * IND];
__device__ __half g_Wsmhi[192 * IND];
__device__ __half g_Wsmlo[192 * IND];
__device__ int   g_hist[NN];
__device__ int   g_off[NN + 1];
__device__ int   g_cursor[NN];
__device__ int   g_sorted[EE];

// ---------------- helpers ----------------
__device__ __forceinline__ uint32_t smem_u32(const void* p) {
    uint32_t a;
    asm("{ .reg .u64 t; cvta.to.shared.u64 t, %1; cvt.u32.u64 %0, t; }" : "=r"(a) : "l"(p));
    return a;
}
__device__ __forceinline__ void ldm4(uint32_t* r, uint32_t addr) {
    asm volatile("ldmatrix.sync.aligned.m8n8.x4.shared.b16 {%0,%1,%2,%3}, [%4];"
                 : "=r"(r[0]), "=r"(r[1]), "=r"(r[2]), "=r"(r[3]) : "r"(addr));
}
__device__ __forceinline__ void mma16816(float* d, const uint32_t* a, uint32_t b0, uint32_t b1) {
    asm volatile(
        "mma.sync.aligned.m16n8k16.row.col.f32.f16.f16.f32 "
        "{%0,%1,%2,%3}, {%4,%5,%6,%7}, {%8,%9}, {%0,%1,%2,%3};"
        : "+f"(d[0]), "+f"(d[1]), "+f"(d[2]), "+f"(d[3])
        : "r"(a[0]), "r"(a[1]), "r"(a[2]), "r"(a[3]), "r"(b0), "r"(b1));
}
// sync tile load: rows of 128 fp16 (256B), 16B chunk ch swizzled (ch^row)&7
__device__ __forceinline__ void ld_tile_n(const __half* __restrict__ src, int row0,
                                          char* dst, int tid, int nrows) {
    for (int idx = tid; idx < nrows * 16; idx += 256) {
        int row = idx >> 4, ch = idx & 15;
        uint4 v = *(const uint4*)(src + (size_t)(row0 + row) * IND + ch * 8);
        *(uint4*)(dst + row * 256 + ((((ch & 7) ^ (row & 7)) << 4) + ((ch & 8) << 4))) = v;
    }
}

// ---------------- fold1 v3: one block per d; esT in smem; writes fp16 Whi + b1f ------
#define FOLD1_SMEM 49920
__global__ __launch_bounds__(256) void k_fold1(const float* __restrict__ p1w,
                                               const float* __restrict__ p1b,
                                               const float* __restrict__ e3w,
                                               const float* __restrict__ gam,
                                               const float* __restrict__ var) {
    extern __shared__ float fs[];
    float* hp  = fs;             // 8192  : p1w rows (j<<6)|d, [j][k]
    float* esT = fs + 8192;      // 64*65 : e3w transposed, [j][jp] stride 65
    float* pb  = fs + 12352;     // 64
    float* ss  = fs + 12416;     // 64
    int d = blockIdx.x, tid = threadIdx.x;
    for (int idx = tid; idx < 8192; idx += 256) {
        int j = idx >> 7, k = idx & 127;
        hp[idx] = p1w[(size_t)((j << 6) | d) * IND + k];
    }
    for (int idx = tid; idx < 4096; idx += 256) {
        int jp = idx >> 6, j = idx & 63;
        esT[j * 65 + jp] = e3w[idx];
    }
    if (tid < 64) {
        pb[tid] = p1b[(tid << 6) | d];
        ss[tid] = gam[tid] * rsqrtf(var[tid] + 1e-5f);
    }
    __syncthreads();

    int kq = tid & 31, jg = tid >> 5;   // k = kq*4.., jp = jg*8..
    float acc[8][4];
#pragma unroll
    for (int jj = 0; jj < 8; ++jj)
#pragma unroll
        for (int kk = 0; kk < 4; ++kk) acc[jj][kk] = 0.f;

#pragma unroll 2
    for (int j = 0; j < 64; ++j) {
        float4 hv = *(float4*)&hp[j * 128 + kq * 4];
        const float* ej = &esT[j * 65 + jg * 8];
#pragma unroll
        for (int jj = 0; jj < 8; ++jj) {
            float e = ej[jj];
            acc[jj][0] += e * hv.x;
            acc[jj][1] += e * hv.y;
            acc[jj][2] += e * hv.z;
            acc[jj][3] += e * hv.w;
        }
    }
#pragma unroll
    for (int jj = 0; jj < 8; ++jj) {
        int jp = jg * 8 + jj;
        float s = ss[jp];
        size_t ro = (size_t)((d << 6) | jp) * IND + kq * 4;
#pragma unroll
        for (int kk = 0; kk < 4; ++kk)
            g_Whi[ro + kk] = __float2half(s * acc[jj][kk]);
    }
    if (tid < 64) {
        float b = 0.f;
        for (int j = 0; j < 64; ++j) b += esT[j * 65 + tid] * pb[j];
        g_b1f[(d << 6) | tid] = ss[tid] * b;
    }
}

// ---------------- fold2 (+ hist zero + Call fold), fp16 split small weights ----------
__global__ void k_fold2(const float* __restrict__ p2w, const float* __restrict__ p2b,
                        const float* __restrict__ convw, const float* __restrict__ e2w,
                        const float* __restrict__ gam, const float* __restrict__ var,
                        const float* __restrict__ e2b, const float* __restrict__ e3b,
                        const float* __restrict__ convb, const float* __restrict__ bet,
                        const float* __restrict__ mean) {
    int c = blockIdx.x;            // 0..191
    int k = threadIdx.x;           // 0..127
    int gi = c * 128 + k;
    if (gi < NN) g_hist[gi] = 0;

    float val;
    if (c < 64) {
        val = p2w[c * IND + k];
        if (k == 0) g_bsm[c] = p2b[c];
    } else {
        int j  = (c - 64) & 63;
        int cc = (c >= 128) ? 1 : 0;
        float s = gam[j] * rsqrtf(var[j] + 1e-5f);
        float a = 0.f;
#pragma unroll
        for (int u = 0; u < 3; ++u) {
            int i = k - u + 1;
            if (i >= 0 && i < IND) a += convw[cc * 3 + u] * e2w[j * IND + i];
        }
        val = s * a;
        if (k == 0) g_bsm[c] = 0.f;
    }
    __half hi = __float2half(val);
    g_Wsmhi[c * IND + k] = hi;
    g_Wsmlo[c * IND + k] = __float2half(val - __half2float(hi));

    if (c == 0 && k < 64) {
        float s = gam[k] * rsqrtf(var[k] + 1e-5f);
        float t = bet[k] - mean[k] * s;
        float rs = 0.f;
        for (int i = 0; i < IND; ++i) rs += e2w[k * IND + i];
        g_Call[k] = s * (convb[0] * rs + e2b[k] + e3b[k]) + t;
    }
}

// ---------------- fp16 split of h (+ edge histogram) ----------------
__global__ void k_convert_h(const float* __restrict__ h, const int* __restrict__ src) {
    int i = blockIdx.x * 256 + threadIdx.x;   // 262144 threads, x4 elems
    float4 v = ((const float4*)h)[i];
    __half h0 = __float2half(v.x), h1 = __float2half(v.y);
    __half h2 = __float2half(v.z), h3 = __float2half(v.w);
    __half2* Hh = (__half2*)g_Hhi;
    __half2* Hl = (__half2*)g_Hlo;
    Hh[2 * i]     = __half2(h0, h1);
    Hh[2 * i + 1] = __half2(h2, h3);
    Hl[2 * i]     = __half2(__float2half(v.x - __half2float(h0)),
                            __float2half(v.y - __half2float(h1)));
    Hl[2 * i + 1] = __half2(__float2half(v.z - __half2float(h2)),
                            __float2half(v.w - __half2float(h3)));
    if (i < EE) atomicAdd(&g_hist[src[i]], 1);
}

// ---------------- big-GEMM mainloop pass (warp tile 64x32, 2x4 warps) ----------------
__device__ __forceinline__ void gemm_pass(uint32_t aBase, uint32_t bBase,
                                          int wm, int wn, int rbase, int khalf,
                                          float (*acc)[4][4]) {
#pragma unroll
    for (int ks = 0; ks < 8; ++ks) {
        int kch = (ks * 16 + khalf) >> 3;
        uint32_t a[4][4];
#pragma unroll
        for (int mt = 0; mt < 4; ++mt) {
            int row = wm * 64 + mt * 16 + rbase;
            ldm4(a[mt], aBase + row * 256 +
                        ((((kch & 7) ^ (row & 7)) << 4) + ((kch & 8) << 4)));
        }
        uint32_t b[2][4];
#pragma unroll
        for (int bt = 0; bt < 2; ++bt) {
            int row = wn * 32 + bt * 16 + rbase;
            ldm4(b[bt], bBase + row * 256 +
                        ((((kch & 7) ^ (row & 7)) << 4) + ((kch & 8) << 4)));
        }
#pragma unroll
        for (int mt = 0; mt < 4; ++mt)
#pragma unroll
            for (int nt = 0; nt < 4; ++nt)
                mma16816(acc[mt][nt], a[mt],
                         b[nt >> 1][nt & 1], b[nt >> 1][(nt & 1) + 2]);
    }
}

// ---------------- fused GEMM kernel, 112KB smem, 2 CTAs/SM ----------------
// bid < 128  : small GEMM tile (M=128 x N=96 of S), fp16 3-pass
// bid >= 128 : big GEMM tile 128x128 (A' = h@W1f^T+b1f), fp16 2-pass
#define FU_A_HI 0
#define FU_A_LO 32768
#define FU_B_HI 65536
#define FU_B_LO 90112
#define FU_SMEM 114688

__global__ __launch_bounds__(256, 2) void k_gemm_fused() {
    extern __shared__ char smem[];
    int bid = blockIdx.x;
    int tid = threadIdx.x;
    int warp = tid >> 5, lane = tid & 31;
    uint32_t sbase = smem_u32(smem);
    int rbase = lane & 15;
    int khalf = (lane >> 4) << 3;

    if (bid >= 128) {
        // ---- big GEMM ----
        int g  = bid - 128;
        int r0 = (g & 31) * 128;     // N (W1f rows)
        int m0 = (g >> 5) * 128;     // M (nodes)

        ld_tile_n(g_Hhi, m0, smem + FU_A_HI, tid, 128);
        ld_tile_n(g_Hlo, m0, smem + FU_A_LO, tid, 128);
        ld_tile_n(g_Whi, r0, smem + FU_B_HI, tid, 128);
        __syncthreads();

        int wm = warp & 1, wn = warp >> 1;          // 2 x 4
        float acc[4][4][4];
#pragma unroll
        for (int mt = 0; mt < 4; ++mt)
#pragma unroll
            for (int nt = 0; nt < 4; ++nt)
#pragma unroll
                for (int i = 0; i < 4; ++i) acc[mt][nt][i] = 0.f;

        gemm_pass(sbase + FU_A_HI, sbase + FU_B_HI, wm, wn, rbase, khalf, acc);
        gemm_pass(sbase + FU_A_LO, sbase + FU_B_HI, wm, wn, rbase, khalf, acc);

        int gr = lane >> 2, gc = (lane & 3) * 2;
#pragma unroll
        for (int nt = 0; nt < 4; ++nt) {
            int col = r0 + wn * 32 + nt * 8 + gc;
            float b0 = g_b1f[col], b1 = g_b1f[col + 1];
#pragma unroll
            for (int mt = 0; mt < 4; ++mt) {
                int row = m0 + wm * 64 + mt * 16 + gr;
                float2 v0 = { acc[mt][nt][0] + b0, acc[mt][nt][1] + b1 };
                float2 v1 = { acc[mt][nt][2] + b0, acc[mt][nt][3] + b1 };
                *(float2*)&g_A[(size_t)row * RDIM + col]       = v0;
                *(float2*)&g_A[(size_t)(row + 8) * RDIM + col] = v1;
            }
        }
    } else {
        // ---- small GEMM: S tile (M=128 x N=96), 3 passes ----
        int m0 = (bid >> 1) * 128;
        int n0 = (bid & 1) * 96;
        ld_tile_n(g_Hhi,   m0, smem + FU_A_HI, tid, 128);
        ld_tile_n(g_Hlo,   m0, smem + FU_A_LO, tid, 128);
        ld_tile_n(g_Wsmhi + n0 * IND, 0, smem + FU_B_HI, tid, 96);
        ld_tile_n(g_Wsmlo + n0 * IND, 0, smem + FU_B_LO, tid, 96);
        __syncthreads();

        int wm = warp & 3, wn = warp >> 2;   // 4 x 2, warp tile 32x48
        float acc[2][6][4];
#pragma unroll
        for (int mt = 0; mt < 2; ++mt)
#pragma unroll
            for (int nt = 0; nt < 6; ++nt)
#pragma unroll
                for (int i = 0; i < 4; ++i) acc[mt][nt][i] = 0.f;

#pragma unroll 1
        for (int pass = 0; pass < 3; ++pass) {
            uint32_t aBase = sbase + ((pass == 2) ? FU_A_LO : FU_A_HI);
            uint32_t bBase = sbase + ((pass == 1) ? FU_B_LO : FU_B_HI);
#pragma unroll
            for (int ks = 0; ks < 8; ++ks) {
                int kch = (ks * 16 + khalf) >> 3;
                uint32_t a[2][4];
#pragma unroll
                for (int mt = 0; mt < 2; ++mt) {
                    int row = wm * 32 + mt * 16 + rbase;
                    ldm4(a[mt], aBase + row * 256 +
                                ((((kch & 7) ^ (row & 7)) << 4) + ((kch & 8) << 4)));
                }
                uint32_t b[3][4];
#pragma unroll
                for (int bt = 0; bt < 3; ++bt) {
                    int row = wn * 48 + bt * 16 + rbase;
                    ldm4(b[bt], bBase + row * 256 +
                                ((((kch & 7) ^ (row & 7)) << 4) + ((kch & 8) << 4)));
                }
#pragma unroll
                for (int mt = 0; mt < 2; ++mt)
#pragma unroll
                    for (int nt = 0; nt < 6; ++nt)
                        mma16816(acc[mt][nt], a[mt],
                                 b[nt >> 1][nt & 1], b[nt >> 1][(nt & 1) + 2]);
            }
        }

        int gr = lane >> 2, gc = (lane & 3) * 2;
#pragma unroll
        for (int nt = 0; nt < 6; ++nt) {
            int col = n0 + wn * 48 + nt * 8 + gc;
            float b0 = g_bsm[col], b1 = g_bsm[col + 1];
#pragma unroll
            for (int mt = 0; mt < 2; ++mt) {
                int row = m0 + wm * 32 + mt * 16 + gr;
                float2 v0 = { acc[mt][nt][0] + b0, acc[mt][nt][1] + b1 };
                float2 v1 = { acc[mt][nt][2] + b0, acc[mt][nt][3] + b1 };
                *(float2*)&g_S[(size_t)row * 192 + col]       = v0;
                *(float2*)&g_S[(size_t)(row + 8) * 192 + col] = v1;
            }
        }
    }
}

// ---------------- counting sort: warp-shuffle scan + scatter ----------------
__global__ void k_scan() {
    __shared__ int ws[32];
    int t = threadIdx.x, lane = t & 31, w = t >> 5;
    int base = t * 8;
    int v[8];
    int s = 0;
#pragma unroll
    for (int i = 0; i < 8; ++i) { v[i] = g_hist[base + i]; s += v[i]; }
    int p = s;
#pragma unroll
    for (int off = 1; off < 32; off <<= 1) {
        int n = __shfl_up_sync(0xffffffffu, p, off);
        if (lane >= off) p += n;
    }
    if (lane == 31) ws[w] = p;
    __syncthreads();
    if (w == 0) {
        int x = ws[lane];
#pragma unroll
        for (int off = 1; off < 32; off <<= 1) {
            int n = __shfl_up_sync(0xffffffffu, x, off);
            if (lane >= off) x += n;
        }
        ws[lane] = x;
    }
    __syncthreads();
    int run = p - s + (w ? ws[w - 1] : 0);   // exclusive prefix for this thread's 8
#pragma unroll
    for (int i = 0; i < 8; ++i) {
        g_off[base + i]    = run;
        g_cursor[base + i] = run;
        run += v[i];
    }
    if (t == 1023) g_off[NN] = run;
}
__global__ void k_scatter(const int* __restrict__ src) {
    int e = blockIdx.x * blockDim.x + threadIdx.x;
    if (e < EE) {
        int p = atomicAdd(&g_cursor[src[e]], 1);
        g_sorted[p] = e;
    }
}

// ---------------- edge kernel ----------------
__global__ __launch_bounds__(64) void k_edge(const int* __restrict__ dst,
                                             float* __restrict__ out) {
    int n = blockIdx.x;
    int beg = g_off[n], end = g_off[n + 1];
    if (beg == end) return;
    int j = threadIdx.x;
    int lane = j & 31;

    float Areg[64];
    const float* Ap = &g_A[(size_t)n * RDIM + j];
#pragma unroll
    for (int d = 0; d < 64; ++d) Areg[d] = Ap[d * 64];

    float cj = g_Call[j] + g_S[(size_t)n * 192 + 64 + j];

    for (int idx = beg; idx < end; ++idx) {
        int e = g_sorted[idx];
        int m = dst[e];
        const float* Sp = &g_S[(size_t)m * 192];
        float p2lo = Sp[lane];
        float p2hi = Sp[32 + lane];
        float acc = cj + Sp[128 + j];
#pragma unroll
        for (int d = 0; d < 32; ++d)
            acc += Areg[d] * __shfl_sync(0xffffffffu, p2lo, d);
#pragma unroll
        for (int d = 0; d < 32; ++d)
            acc += Areg[32 + d] * __shfl_sync(0xffffffffu, p2hi, d);
        out[(size_t)e * 64 + j] = fmaxf(acc, 0.f);
    }
}

// ---------------- launch ----------------
extern "C" void kernel_launch(void* const* d_in, const int* in_sizes, int n_in,
                              void* d_out, int out_size) {
    const float* h     = (const float*)d_in[0];
    const int*   src   = (const int*)  d_in[1];
    const int*   dst   = (const int*)  d_in[2];
    const float* p1w   = (const float*)d_in[3];
    const float* p1b   = (const float*)d_in[4];
    const float* p2w   = (const float*)d_in[5];
    const float* p2b   = (const float*)d_in[6];
    const float* convw = (const float*)d_in[7];
    const float* convb = (const float*)d_in[8];
    const float* e2w   = (const float*)d_in[9];
    const float* e2b   = (const float*)d_in[10];
    const float* e3w   = (const float*)d_in[11];
    const float* e3b   = (const float*)d_in[12];
    const float* gam   = (const float*)d_in[13];
    const float* bet   = (const float*)d_in[14];
    const float* mean  = (const float*)d_in[15];
    const float* var   = (const float*)d_in[16];
    float* out = (float*)d_out;

    cudaFuncSetAttribute(k_fold1,      cudaFuncAttributeMaxDynamicSharedMemorySize, FOLD1_SMEM);
    cudaFuncSetAttribute(k_gemm_fused, cudaFuncAttributeMaxDynamicSharedMemorySize, FU_SMEM);

    k_fold1<<<64, 256, FOLD1_SMEM>>>(p1w, p1b, e3w, gam, var);
    k_fold2<<<192, 128>>>(p2w, p2b, convw, e2w, gam, var, e2b, e3b, convb, bet, mean);
    k_convert_h<<<1024, 256>>>(h, src);
    k_scan<<<1, 1024>>>();
    k_scatter<<<(EE + 255) / 256, 256>>>(src);
    k_gemm_fused<<<128 + NN / 128 * (RDIM / 128), 256, FU_SMEM>>>();
    k_edge<<<NN, 64>>>(dst, out);
}

// round 14
// speedup vs baseline: 1.9292x; 1.0764x over previous
#include <cuda_runtime.h>
#include <cuda_fp16.h>
#include <cstdint>

#define NN   8192
#define EE   65536
#define IND  128
#define HID  64
#define RDIM 4096   // HID*HID

// ---------------- static scratch (no allocs allowed) ----------------
__device__ __half g_A[(size_t)NN * RDIM];      // A' [n][d*64 + j], BN folded (64 MB, fp16)
__device__ float g_S[NN * 192];                // per-node: p2 | qs | qd
__device__ float g_b1f[RDIM];
__device__ float g_bsm[192];
__device__ float g_Call[HID];
__device__ __half g_Hhi[(size_t)NN * IND];
__device__ __half g_Hlo[(size_t)NN * IND];
__device__ __half g_Whi[(size_t)RDIM * IND];
__device__ __half g_Wsmhi[192 * IND];
__device__ __half g_Wsmlo[192 * IND];
__device__ int   g_hist[NN];
__device__ int   g_off[NN + 1];
__device__ int   g_cursor[NN];
__device__ int   g_sorted[EE];

// ---------------- helpers ----------------
__device__ __forceinline__ uint32_t smem_u32(const void* p) {
    uint32_t a;
    asm("{ .reg .u64 t; cvta.to.shared.u64 t, %1; cvt.u32.u64 %0, t; }" : "=r"(a) : "l"(p));
    return a;
}
__device__ __forceinline__ void ldm4(uint32_t* r, uint32_t addr) {
    asm volatile("ldmatrix.sync.aligned.m8n8.x4.shared.b16 {%0,%1,%2,%3}, [%4];"
                 : "=r"(r[0]), "=r"(r[1]), "=r"(r[2]), "=r"(r[3]) : "r"(addr));
}
__device__ __forceinline__ void mma16816(float* d, const uint32_t* a, uint32_t b0, uint32_t b1) {
    asm volatile(
        "mma.sync.aligned.m16n8k16.row.col.f32.f16.f16.f32 "
        "{%0,%1,%2,%3}, {%4,%5,%6,%7}, {%8,%9}, {%0,%1,%2,%3};"
        : "+f"(d[0]), "+f"(d[1]), "+f"(d[2]), "+f"(d[3])
        : "r"(a[0]), "r"(a[1]), "r"(a[2]), "r"(a[3]), "r"(b0), "r"(b1));
}
// sync tile load: rows of 128 fp16 (256B), 16B chunk ch swizzled (ch^row)&7
__device__ __forceinline__ void ld_tile_n(const __half* __restrict__ src, int row0,
                                          char* dst, int tid, int nrows) {
    for (int idx = tid; idx < nrows * 16; idx += 256) {
        int row = idx >> 4, ch = idx & 15;
        uint4 v = *(const uint4*)(src + (size_t)(row0 + row) * IND + ch * 8);
        *(uint4*)(dst + row * 256 + ((((ch & 7) ^ (row & 7)) << 4) + ((ch & 8) << 4))) = v;
    }
}

// ---------------- fold1 v3: one block per d; esT in smem; writes fp16 Whi + b1f ------
#define FOLD1_SMEM 49920
__global__ __launch_bounds__(256) void k_fold1(const float* __restrict__ p1w,
                                               const float* __restrict__ p1b,
                                               const float* __restrict__ e3w,
                                               const float* __restrict__ gam,
                                               const float* __restrict__ var) {
    extern __shared__ float fs[];
    float* hp  = fs;             // 8192  : p1w rows (j<<6)|d, [j][k]
    float* esT = fs + 8192;      // 64*65 : e3w transposed, [j][jp] stride 65
    float* pb  = fs + 12352;     // 64
    float* ss  = fs + 12416;     // 64
    int d = blockIdx.x, tid = threadIdx.x;
    for (int idx = tid; idx < 8192; idx += 256) {
        int j = idx >> 7, k = idx & 127;
        hp[idx] = p1w[(size_t)((j << 6) | d) * IND + k];
    }
    for (int idx = tid; idx < 4096; idx += 256) {
        int jp = idx >> 6, j = idx & 63;
        esT[j * 65 + jp] = e3w[idx];
    }
    if (tid < 64) {
        pb[tid] = p1b[(tid << 6) | d];
        ss[tid] = gam[tid] * rsqrtf(var[tid] + 1e-5f);
    }
    __syncthreads();

    int kq = tid & 31, jg = tid >> 5;   // k = kq*4.., jp = jg*8..
    float acc[8][4];
#pragma unroll
    for (int jj = 0; jj < 8; ++jj)
#pragma unroll
        for (int kk = 0; kk < 4; ++kk) acc[jj][kk] = 0.f;

#pragma unroll 2
    for (int j = 0; j < 64; ++j) {
        float4 hv = *(float4*)&hp[j * 128 + kq * 4];
        const float* ej = &esT[j * 65 + jg * 8];
#pragma unroll
        for (int jj = 0; jj < 8; ++jj) {
            float e = ej[jj];
            acc[jj][0] += e * hv.x;
            acc[jj][1] += e * hv.y;
            acc[jj][2] += e * hv.z;
            acc[jj][3] += e * hv.w;
        }
    }
#pragma unroll
    for (int jj = 0; jj < 8; ++jj) {
        int jp = jg * 8 + jj;
        float s = ss[jp];
        size_t ro = (size_t)((d << 6) | jp) * IND + kq * 4;
#pragma unroll
        for (int kk = 0; kk < 4; ++kk)
            g_Whi[ro + kk] = __float2half(s * acc[jj][kk]);
    }
    if (tid < 64) {
        float b = 0.f;
        for (int j = 0; j < 64; ++j) b += esT[j * 65 + tid] * pb[j];
        g_b1f[(d << 6) | tid] = ss[tid] * b;
    }
}

// ---------------- fold2 (+ hist zero + Call fold), fp16 split small weights ----------
__global__ void k_fold2(const float* __restrict__ p2w, const float* __restrict__ p2b,
                        const float* __restrict__ convw, const float* __restrict__ e2w,
                        const float* __restrict__ gam, const float* __restrict__ var,
                        const float* __restrict__ e2b, const float* __restrict__ e3b,
                        const float* __restrict__ convb, const float* __restrict__ bet,
                        const float* __restrict__ mean) {
    int c = blockIdx.x;            // 0..191
    int k = threadIdx.x;           // 0..127
    int gi = c * 128 + k;
    if (gi < NN) g_hist[gi] = 0;

    float val;
    if (c < 64) {
        val = p2w[c * IND + k];
        if (k == 0) g_bsm[c] = p2b[c];
    } else {
        int j  = (c - 64) & 63;
        int cc = (c >= 128) ? 1 : 0;
        float s = gam[j] * rsqrtf(var[j] + 1e-5f);
        float a = 0.f;
#pragma unroll
        for (int u = 0; u < 3; ++u) {
            int i = k - u + 1;
            if (i >= 0 && i < IND) a += convw[cc * 3 + u] * e2w[j * IND + i];
        }
        val = s * a;
        if (k == 0) g_bsm[c] = 0.f;
    }
    __half hi = __float2half(val);
    g_Wsmhi[c * IND + k] = hi;
    g_Wsmlo[c * IND + k] = __float2half(val - __half2float(hi));

    if (c == 0 && k < 64) {
        float s = gam[k] * rsqrtf(var[k] + 1e-5f);
        float t = bet[k] - mean[k] * s;
        float rs = 0.f;
        for (int i = 0; i < IND; ++i) rs += e2w[k * IND + i];
        g_Call[k] = s * (convb[0] * rs + e2b[k] + e3b[k]) + t;
    }
}

// ---------------- fp16 split of h (+ edge histogram), 8 elems/thread ----------------
__global__ void k_convert_h(const float* __restrict__ h, const int* __restrict__ src) {
    int i = blockIdx.x * 256 + threadIdx.x;   // grid 512 -> 131072 threads, x8 elems
    __half2* Hh = (__half2*)g_Hhi;
    __half2* Hl = (__half2*)g_Hlo;
#pragma unroll
    for (int q = 0; q < 2; ++q) {
        int ii = 2 * i + q;
        float4 v = ((const float4*)h)[ii];
        __half h0 = __float2half(v.x), h1 = __float2half(v.y);
        __half h2 = __float2half(v.z), h3 = __float2half(v.w);
        Hh[2 * ii]     = __half2(h0, h1);
        Hh[2 * ii + 1] = __half2(h2, h3);
        Hl[2 * ii]     = __half2(__float2half(v.x - __half2float(h0)),
                                 __float2half(v.y - __half2float(h1)));
        Hl[2 * ii + 1] = __half2(__float2half(v.z - __half2float(h2)),
                                 __float2half(v.w - __half2float(h3)));
    }
    if (i < EE) atomicAdd(&g_hist[src[i]], 1);
}

// ---------------- big-GEMM mainloop pass (warp tile 64x32, 2x4 warps) ----------------
__device__ __forceinline__ void gemm_pass(uint32_t aBase, uint32_t bBase,
                                          int wm, int wn, int rbase, int khalf,
                                          float (*acc)[4][4]) {
#pragma unroll
    for (int ks = 0; ks < 8; ++ks) {
        int kch = (ks * 16 + khalf) >> 3;
        uint32_t a[4][4];
#pragma unroll
        for (int mt = 0; mt < 4; ++mt) {
            int row = wm * 64 + mt * 16 + rbase;
            ldm4(a[mt], aBase + row * 256 +
                        ((((kch & 7) ^ (row & 7)) << 4) + ((kch & 8) << 4)));
        }
        uint32_t b[2][4];
#pragma unroll
        for (int bt = 0; bt < 2; ++bt) {
            int row = wn * 32 + bt * 16 + rbase;
            ldm4(b[bt], bBase + row * 256 +
                        ((((kch & 7) ^ (row & 7)) << 4) + ((kch & 8) << 4)));
        }
#pragma unroll
        for (int mt = 0; mt < 4; ++mt)
#pragma unroll
            for (int nt = 0; nt < 4; ++nt)
                mma16816(acc[mt][nt], a[mt],
                         b[nt >> 1][nt & 1], b[nt >> 1][(nt & 1) + 2]);
    }
}

// ---------------- fused GEMM kernel, 112KB smem, 2 CTAs/SM ----------------
// bid < 128  : small GEMM tile (M=128 x N=96 of S), fp16 3-pass
// bid >= 128 : big GEMM tile 128x128 (A' = h@W1f^T+b1f), fp16 2-pass, fp16 store
#define FU_A_HI 0
#define FU_A_LO 32768
#define FU_B_HI 65536
#define FU_B_LO 90112
#define FU_SMEM 114688

__global__ __launch_bounds__(256, 2) void k_gemm_fused() {
    extern __shared__ char smem[];
    int bid = blockIdx.x;
    int tid = threadIdx.x;
    int warp = tid >> 5, lane = tid & 31;
    uint32_t sbase = smem_u32(smem);
    int rbase = lane & 15;
    int khalf = (lane >> 4) << 3;

    if (bid >= 128) {
        // ---- big GEMM ----
        int g  = bid - 128;
        int r0 = (g & 31) * 128;     // N (W1f rows)
        int m0 = (g >> 5) * 128;     // M (nodes)

        ld_tile_n(g_Hhi, m0, smem + FU_A_HI, tid, 128);
        ld_tile_n(g_Hlo, m0, smem + FU_A_LO, tid, 128);
        ld_tile_n(g_Whi, r0, smem + FU_B_HI, tid, 128);
        __syncthreads();

        int wm = warp & 1, wn = warp >> 1;          // 2 x 4
        float acc[4][4][4];
#pragma unroll
        for (int mt = 0; mt < 4; ++mt)
#pragma unroll
            for (int nt = 0; nt < 4; ++nt)
#pragma unroll
                for (int i = 0; i < 4; ++i) acc[mt][nt][i] = 0.f;

        gemm_pass(sbase + FU_A_HI, sbase + FU_B_HI, wm, wn, rbase, khalf, acc);
        gemm_pass(sbase + FU_A_LO, sbase + FU_B_HI, wm, wn, rbase, khalf, acc);

        int gr = lane >> 2, gc = (lane & 3) * 2;
#pragma unroll
        for (int nt = 0; nt < 4; ++nt) {
            int col = r0 + wn * 32 + nt * 8 + gc;
            float b0 = g_b1f[col], b1 = g_b1f[col + 1];
#pragma unroll
            for (int mt = 0; mt < 4; ++mt) {
                int row = m0 + wm * 64 + mt * 16 + gr;
                *(__half2*)&g_A[(size_t)row * RDIM + col] =
                    __floats2half2_rn(acc[mt][nt][0] + b0, acc[mt][nt][1] + b1);
                *(__half2*)&g_A[(size_t)(row + 8) * RDIM + col] =
                    __floats2half2_rn(acc[mt][nt][2] + b0, acc[mt][nt][3] + b1);
            }
        }
    } else {
        // ---- small GEMM: S tile (M=128 x N=96), 3 passes ----
        int m0 = (bid >> 1) * 128;
        int n0 = (bid & 1) * 96;
        ld_tile_n(g_Hhi,   m0, smem + FU_A_HI, tid, 128);
        ld_tile_n(g_Hlo,   m0, smem + FU_A_LO, tid, 128);
        ld_tile_n(g_Wsmhi + n0 * IND, 0, smem + FU_B_HI, tid, 96);
        ld_tile_n(g_Wsmlo + n0 * IND, 0, smem + FU_B_LO, tid, 96);
        __syncthreads();

        int wm = warp & 3, wn = warp >> 2;   // 4 x 2, warp tile 32x48
        float acc[2][6][4];
#pragma unroll
        for (int mt = 0; mt < 2; ++mt)
#pragma unroll
            for (int nt = 0; nt < 6; ++nt)
#pragma unroll
                for (int i = 0; i < 4; ++i) acc[mt][nt][i] = 0.f;

#pragma unroll 1
        for (int pass = 0; pass < 3; ++pass) {
            uint32_t aBase = sbase + ((pass == 2) ? FU_A_LO : FU_A_HI);
            uint32_t bBase = sbase + ((pass == 1) ? FU_B_LO : FU_B_HI);
#pragma unroll
            for (int ks = 0; ks < 8; ++ks) {
                int kch = (ks * 16 + khalf) >> 3;
                uint32_t a[2][4];
#pragma unroll
                for (int mt = 0; mt < 2; ++mt) {
                    int row = wm * 32 + mt * 16 + rbase;
                    ldm4(a[mt], aBase + row * 256 +
                                ((((kch & 7) ^ (row & 7)) << 4) + ((kch & 8) << 4)));
                }
                uint32_t b[3][4];
#pragma unroll
                for (int bt = 0; bt < 3; ++bt) {
                    int row = wn * 48 + bt * 16 + rbase;
                    ldm4(b[bt], bBase + row * 256 +
                                ((((kch & 7) ^ (row & 7)) << 4) + ((kch & 8) << 4)));
                }
#pragma unroll
                for (int mt = 0; mt < 2; ++mt)
#pragma unroll
                    for (int nt = 0; nt < 6; ++nt)
                        mma16816(acc[mt][nt], a[mt],
                                 b[nt >> 1][nt & 1], b[nt >> 1][(nt & 1) + 2]);
            }
        }

        int gr = lane >> 2, gc = (lane & 3) * 2;
#pragma unroll
        for (int nt = 0; nt < 6; ++nt) {
            int col = n0 + wn * 48 + nt * 8 + gc;
            float b0 = g_bsm[col], b1 = g_bsm[col + 1];
#pragma unroll
            for (int mt = 0; mt < 2; ++mt) {
                int row = m0 + wm * 32 + mt * 16 + gr;
                float2 v0 = { acc[mt][nt][0] + b0, acc[mt][nt][1] + b1 };
                float2 v1 = { acc[mt][nt][2] + b0, acc[mt][nt][3] + b1 };
                *(float2*)&g_S[(size_t)row * 192 + col]       = v0;
                *(float2*)&g_S[(size_t)(row + 8) * 192 + col] = v1;
            }
        }
    }
}

// ---------------- counting sort: warp-shuffle scan (int4 loads) + scatter ------------
__global__ void k_scan() {
    __shared__ int ws[32];
    int t = threadIdx.x, lane = t & 31, w = t >> 5;
    int base = t * 8;
    int4 a = ((const int4*)g_hist)[t * 2];
    int4 b = ((const int4*)g_hist)[t * 2 + 1];
    int v[8] = { a.x, a.y, a.z, a.w, b.x, b.y, b.z, b.w };
    int s = 0;
#pragma unroll
    for (int i = 0; i < 8; ++i) s += v[i];
    int p = s;
#pragma unroll
    for (int off = 1; off < 32; off <<= 1) {
        int n = __shfl_up_sync(0xffffffffu, p, off);
        if (lane >= off) p += n;
    }
    if (lane == 31) ws[w] = p;
    __syncthreads();
    if (w == 0) {
        int x = ws[lane];
#pragma unroll
        for (int off = 1; off < 32; off <<= 1) {
            int n = __shfl_up_sync(0xffffffffu, x, off);
            if (lane >= off) x += n;
        }
        ws[lane] = x;
    }
    __syncthreads();
    int run = p - s + (w ? ws[w - 1] : 0);   // exclusive prefix for this thread's 8
#pragma unroll
    for (int i = 0; i < 8; ++i) {
        g_off[base + i]    = run;
        g_cursor[base + i] = run;
        run += v[i];
    }
    if (t == 1023) g_off[NN] = run;
}
__global__ void k_scatter(const int* __restrict__ src) {
    int e = blockIdx.x * blockDim.x + threadIdx.x;
    if (e < EE) {
        int p = atomicAdd(&g_cursor[src[e]], 1);
        g_sorted[p] = e;
    }
}

// ---------------- edge kernel (fp16 A) ----------------
__global__ __launch_bounds__(64) void k_edge(const int* __restrict__ dst,
                                             float* __restrict__ out) {
    int n = blockIdx.x;
    int beg = g_off[n], end = g_off[n + 1];
    if (beg == end) return;
    int j = threadIdx.x;
    int lane = j & 31;

    float Areg[64];
    const __half* Ap = &g_A[(size_t)n * RDIM + j];
#pragma unroll
    for (int d = 0; d < 64; ++d) Areg[d] = __half2float(Ap[d * 64]);

    float cj = g_Call[j] + g_S[(size_t)n * 192 + 64 + j];

    for (int idx = beg; idx < end; ++idx) {
        int e = g_sorted[idx];
        int m = dst[e];
        const float* Sp = &g_S[(size_t)m * 192];
        float p2lo = Sp[lane];
        float p2hi = Sp[32 + lane];
        float acc = cj + Sp[128 + j];
#pragma unroll
        for (int d = 0; d < 32; ++d)
            acc += Areg[d] * __shfl_sync(0xffffffffu, p2lo, d);
#pragma unroll
        for (int d = 0; d < 32; ++d)
            acc += Areg[32 + d] * __shfl_sync(0xffffffffu, p2hi, d);
        out[(size_t)e * 64 + j] = fmaxf(acc, 0.f);
    }
}

// ---------------- launch ----------------
extern "C" void kernel_launch(void* const* d_in, const int* in_sizes, int n_in,
                              void* d_out, int out_size) {
    const float* h     = (const float*)d_in[0];
    const int*   src   = (const int*)  d_in[1];
    const int*   dst   = (const int*)  d_in[2];
    const float* p1w   = (const float*)d_in[3];
    const float* p1b   = (const float*)d_in[4];
    const float* p2w   = (const float*)d_in[5];
    const float* p2b   = (const float*)d_in[6];
    const float* convw = (const float*)d_in[7];
    const float* convb = (const float*)d_in[8];
    const float* e2w   = (const float*)d_in[9];
    const float* e2b   = (const float*)d_in[10];
    const float* e3w   = (const float*)d_in[11];
    const float* e3b   = (const float*)d_in[12];
    const float* gam   = (const float*)d_in[13];
    const float* bet   = (const float*)d_in[14];
    const float* mean  = (const float*)d_in[15];
    const float* var   = (const float*)d_in[16];
    float* out = (float*)d_out;

    cudaFuncSetAttribute(k_fold1,      cudaFuncAttributeMaxDynamicSharedMemorySize, FOLD1_SMEM);
    cudaFuncSetAttribute(k_gemm_fused, cudaFuncAttributeMaxDynamicSharedMemorySize, FU_SMEM);

    k_fold1<<<64, 256, FOLD1_SMEM>>>(p1w, p1b, e3w, gam, var);
    k_fold2<<<192, 128>>>(p2w, p2b, convw, e2w, gam, var, e2b, e3b, convb, bet, mean);
    k_convert_h<<<512, 256>>>(h, src);
    k_scan<<<1, 1024>>>();
    k_scatter<<<(EE + 255) / 256, 256>>>(src);
    k_gemm_fused<<<128 + NN / 128 * (RDIM / 128), 256, FU_SMEM>>>();
    k_edge<<<NN, 64>>>(dst, out);
}

// round 15
// speedup vs baseline: 2.3691x; 1.2280x over previous
#include <cuda_runtime.h>
#include <cuda_fp16.h>
#include <cstdint>

#define NN   8192
#define EE   65536
#define IND  128
#define HID  64
#define RDIM 4096   // HID*HID

// ---------------- static scratch (no allocs allowed) ----------------
__device__ __half g_A[(size_t)NN * RDIM];      // A' [n][d*64 + j], BN folded (64 MB, fp16)
__device__ float g_S[NN * 192];                // per-node: p2 | qs | qd
__device__ float g_b1f[RDIM];
__device__ float g_bsm[192];
__device__ float g_Call[HID];
__device__ __half g_Hhi[(size_t)NN * IND];
__device__ __half g_Hlo[(size_t)NN * IND];
__device__ __half g_Whi[(size_t)RDIM * IND];
__device__ __half g_Wsmhi[192 * IND];
__device__ __half g_Wsmlo[192 * IND];
__device__ int   g_hist[NN];
__device__ int   g_off[NN + 1];
__device__ int   g_cursor[NN];
__device__ int   g_sorted[EE];
__device__ int   g_bs[64];
__device__ int   g_bspre[64];

// ---------------- helpers ----------------
__device__ __forceinline__ uint32_t smem_u32(const void* p) {
    uint32_t a;
    asm("{ .reg .u64 t; cvta.to.shared.u64 t, %1; cvt.u32.u64 %0, t; }" : "=r"(a) : "l"(p));
    return a;
}
__device__ __forceinline__ void ldm4(uint32_t* r, uint32_t addr) {
    asm volatile("ldmatrix.sync.aligned.m8n8.x4.shared.b16 {%0,%1,%2,%3}, [%4];"
                 : "=r"(r[0]), "=r"(r[1]), "=r"(r[2]), "=r"(r[3]) : "r"(addr));
}
__device__ __forceinline__ void mma16816(float* d, const uint32_t* a, uint32_t b0, uint32_t b1) {
    asm volatile(
        "mma.sync.aligned.m16n8k16.row.col.f32.f16.f16.f32 "
        "{%0,%1,%2,%3}, {%4,%5,%6,%7}, {%8,%9}, {%0,%1,%2,%3};"
        : "+f"(d[0]), "+f"(d[1]), "+f"(d[2]), "+f"(d[3])
        : "r"(a[0]), "r"(a[1]), "r"(a[2]), "r"(a[3]), "r"(b0), "r"(b1));
}
// sync tile load: rows of 128 fp16 (256B), 16B chunk ch swizzled (ch^row)&7
__device__ __forceinline__ void ld_tile_n(const __half* __restrict__ src, int row0,
                                          char* dst, int tid, int nrows) {
    for (int idx = tid; idx < nrows * 16; idx += 256) {
        int row = idx >> 4, ch = idx & 15;
        uint4 v = *(const uint4*)(src + (size_t)(row0 + row) * IND + ch * 8);
        *(uint4*)(dst + row * 256 + ((((ch & 7) ^ (row & 7)) << 4) + ((ch & 8) << 4))) = v;
    }
}

// ---------------- fold1 v3: one block per d; esT in smem; writes fp16 Whi + b1f ------
#define FOLD1_SMEM 49920
__global__ __launch_bounds__(256) void k_fold1(const float* __restrict__ p1w,
                                               const float* __restrict__ p1b,
                                               const float* __restrict__ e3w,
                                               const float* __restrict__ gam,
                                               const float* __restrict__ var) {
    extern __shared__ float fs[];
    float* hp  = fs;             // 8192  : p1w rows (j<<6)|d, [j][k]
    float* esT = fs + 8192;      // 64*65 : e3w transposed, [j][jp] stride 65
    float* pb  = fs + 12352;     // 64
    float* ss  = fs + 12416;     // 64
    int d = blockIdx.x, tid = threadIdx.x;
    for (int idx = tid; idx < 8192; idx += 256) {
        int j = idx >> 7, k = idx & 127;
        hp[idx] = p1w[(size_t)((j << 6) | d) * IND + k];
    }
    for (int idx = tid; idx < 4096; idx += 256) {
        int jp = idx >> 6, j = idx & 63;
        esT[j * 65 + jp] = e3w[idx];
    }
    if (tid < 64) {
        pb[tid] = p1b[(tid << 6) | d];
        ss[tid] = gam[tid] * rsqrtf(var[tid] + 1e-5f);
    }
    __syncthreads();

    int kq = tid & 31, jg = tid >> 5;   // k = kq*4.., jp = jg*8..
    float acc[8][4];
#pragma unroll
    for (int jj = 0; jj < 8; ++jj)
#pragma unroll
        for (int kk = 0; kk < 4; ++kk) acc[jj][kk] = 0.f;

#pragma unroll 2
    for (int j = 0; j < 64; ++j) {
        float4 hv = *(float4*)&hp[j * 128 + kq * 4];
        const float* ej = &esT[j * 65 + jg * 8];
#pragma unroll
        for (int jj = 0; jj < 8; ++jj) {
            float e = ej[jj];
            acc[jj][0] += e * hv.x;
            acc[jj][1] += e * hv.y;
            acc[jj][2] += e * hv.z;
            acc[jj][3] += e * hv.w;
        }
    }
#pragma unroll
    for (int jj = 0; jj < 8; ++jj) {
        int jp = jg * 8 + jj;
        float s = ss[jp];
        size_t ro = (size_t)((d << 6) | jp) * IND + kq * 4;
#pragma unroll
        for (int kk = 0; kk < 4; ++kk)
            g_Whi[ro + kk] = __float2half(s * acc[jj][kk]);
    }
    if (tid < 64) {
        float b = 0.f;
        for (int j = 0; j < 64; ++j) b += esT[j * 65 + tid] * pb[j];
        g_b1f[(d << 6) | tid] = ss[tid] * b;
    }
}

// ---------------- fold2 (+ hist zero + Call fold), fp16 split small weights ----------
__global__ void k_fold2(const float* __restrict__ p2w, const float* __restrict__ p2b,
                        const float* __restrict__ convw, const float* __restrict__ e2w,
                        const float* __restrict__ gam, const float* __restrict__ var,
                        const float* __restrict__ e2b, const float* __restrict__ e3b,
                        const float* __restrict__ convb, const float* __restrict__ bet,
                        const float* __restrict__ mean) {
    int c = blockIdx.x;            // 0..191
    int k = threadIdx.x;           // 0..127
    int gi = c * 128 + k;
    if (gi < NN) g_hist[gi] = 0;

    float val;
    if (c < 64) {
        val = p2w[c * IND + k];
        if (k == 0) g_bsm[c] = p2b[c];
    } else {
        int j  = (c - 64) & 63;
        int cc = (c >= 128) ? 1 : 0;
        float s = gam[j] * rsqrtf(var[j] + 1e-5f);
        float a = 0.f;
#pragma unroll
        for (int u = 0; u < 3; ++u) {
            int i = k - u + 1;
            if (i >= 0 && i < IND) a += convw[cc * 3 + u] * e2w[j * IND + i];
        }
        val = s * a;
        if (k == 0) g_bsm[c] = 0.f;
    }
    __half hi = __float2half(val);
    g_Wsmhi[c * IND + k] = hi;
    g_Wsmlo[c * IND + k] = __float2half(val - __half2float(hi));

    if (c == 0 && k < 64) {
        float s = gam[k] * rsqrtf(var[k] + 1e-5f);
        float t = bet[k] - mean[k] * s;
        float rs = 0.f;
        for (int i = 0; i < IND; ++i) rs += e2w[k * IND + i];
        g_Call[k] = s * (convb[0] * rs + e2b[k] + e3b[k]) + t;
    }
}

// ---------------- fp16 split of h (+ edge histogram), 8 elems/thread ----------------
__global__ void k_convert_h(const float* __restrict__ h, const int* __restrict__ src) {
    int i = blockIdx.x * 256 + threadIdx.x;   // grid 512 -> 131072 threads, x8 elems
    __half2* Hh = (__half2*)g_Hhi;
    __half2* Hl = (__half2*)g_Hlo;
#pragma unroll
    for (int q = 0; q < 2; ++q) {
        int ii = 2 * i + q;
        float4 v = ((const float4*)h)[ii];
        __half h0 = __float2half(v.x), h1 = __float2half(v.y);
        __half h2 = __float2half(v.z), h3 = __float2half(v.w);
        Hh[2 * ii]     = __half2(h0, h1);
        Hh[2 * ii + 1] = __half2(h2, h3);
        Hl[2 * ii]     = __half2(__float2half(v.x - __half2float(h0)),
                                 __float2half(v.y - __half2float(h1)));
        Hl[2 * ii + 1] = __half2(__float2half(v.z - __half2float(h2)),
                                 __float2half(v.w - __half2float(h3)));
    }
    if (i < EE) atomicAdd(&g_hist[src[i]], 1);
}

// ---------------- big-GEMM mainloop pass (warp tile 64x32, 2x4 warps) ----------------
__device__ __forceinline__ void gemm_pass(uint32_t aBase, uint32_t bBase,
                                          int wm, int wn, int rbase, int khalf,
                                          float (*acc)[4][4]) {
#pragma unroll
    for (int ks = 0; ks < 8; ++ks) {
        int kch = (ks * 16 + khalf) >> 3;
        uint32_t a[4][4];
#pragma unroll
        for (int mt = 0; mt < 4; ++mt) {
            int row = wm * 64 + mt * 16 + rbase;
            ldm4(a[mt], aBase + row * 256 +
                        ((((kch & 7) ^ (row & 7)) << 4) + ((kch & 8) << 4)));
        }
        uint32_t b[2][4];
#pragma unroll
        for (int bt = 0; bt < 2; ++bt) {
            int row = wn * 32 + bt * 16 + rbase;
            ldm4(b[bt], bBase + row * 256 +
                        ((((kch & 7) ^ (row & 7)) << 4) + ((kch & 8) << 4)));
        }
#pragma unroll
        for (int mt = 0; mt < 4; ++mt)
#pragma unroll
            for (int nt = 0; nt < 4; ++nt)
                mma16816(acc[mt][nt], a[mt],
                         b[nt >> 1][nt & 1], b[nt >> 1][(nt & 1) + 2]);
    }
}

// ---------------- fused GEMM kernel, 112KB smem, 2 CTAs/SM ----------------
// bid < 128  : small GEMM tile (M=128 x N=96 of S), fp16 3-pass
// bid >= 128 : big GEMM tile 128x128 (A' = h@W1f^T+b1f), fp16 1-pass, fp16 store
#define FU_A_HI 0
#define FU_A_LO 32768
#define FU_B_HI 65536
#define FU_B_LO 90112
#define FU_SMEM 114688

__global__ __launch_bounds__(256, 2) void k_gemm_fused() {
    extern __shared__ char smem[];
    int bid = blockIdx.x;
    int tid = threadIdx.x;
    int warp = tid >> 5, lane = tid & 31;
    uint32_t sbase = smem_u32(smem);
    int rbase = lane & 15;
    int khalf = (lane >> 4) << 3;

    if (bid >= 128) {
        // ---- big GEMM: single fp16 pass (hi x hi) ----
        int g  = bid - 128;
        int r0 = (g & 31) * 128;     // N (W1f rows)
        int m0 = (g >> 5) * 128;     // M (nodes)

        ld_tile_n(g_Hhi, m0, smem + FU_A_HI, tid, 128);
        ld_tile_n(g_Whi, r0, smem + FU_B_HI, tid, 128);
        __syncthreads();

        int wm = warp & 1, wn = warp >> 1;          // 2 x 4
        float acc[4][4][4];
#pragma unroll
        for (int mt = 0; mt < 4; ++mt)
#pragma unroll
            for (int nt = 0; nt < 4; ++nt)
#pragma unroll
                for (int i = 0; i < 4; ++i) acc[mt][nt][i] = 0.f;

        gemm_pass(sbase + FU_A_HI, sbase + FU_B_HI, wm, wn, rbase, khalf, acc);

        int gr = lane >> 2, gc = (lane & 3) * 2;
#pragma unroll
        for (int nt = 0; nt < 4; ++nt) {
            int col = r0 + wn * 32 + nt * 8 + gc;
            float b0 = g_b1f[col], b1 = g_b1f[col + 1];
#pragma unroll
            for (int mt = 0; mt < 4; ++mt) {
                int row = m0 + wm * 64 + mt * 16 + gr;
                *(__half2*)&g_A[(size_t)row * RDIM + col] =
                    __floats2half2_rn(acc[mt][nt][0] + b0, acc[mt][nt][1] + b1);
                *(__half2*)&g_A[(size_t)(row + 8) * RDIM + col] =
                    __floats2half2_rn(acc[mt][nt][2] + b0, acc[mt][nt][3] + b1);
            }
        }
    } else {
        // ---- small GEMM: S tile (M=128 x N=96), 3 passes ----
        int m0 = (bid >> 1) * 128;
        int n0 = (bid & 1) * 96;
        ld_tile_n(g_Hhi,   m0, smem + FU_A_HI, tid, 128);
        ld_tile_n(g_Hlo,   m0, smem + FU_A_LO, tid, 128);
        ld_tile_n(g_Wsmhi + n0 * IND, 0, smem + FU_B_HI, tid, 96);
        ld_tile_n(g_Wsmlo + n0 * IND, 0, smem + FU_B_LO, tid, 96);
        __syncthreads();

        int wm = warp & 3, wn = warp >> 2;   // 4 x 2, warp tile 32x48
        float acc[2][6][4];
#pragma unroll
        for (int mt = 0; mt < 2; ++mt)
#pragma unroll
            for (int nt = 0; nt < 6; ++nt)
#pragma unroll
                for (int i = 0; i < 4; ++i) acc[mt][nt][i] = 0.f;

#pragma unroll 1
        for (int pass = 0; pass < 3; ++pass) {
            uint32_t aBase = sbase + ((pass == 2) ? FU_A_LO : FU_A_HI);
            uint32_t bBase = sbase + ((pass == 1) ? FU_B_LO : FU_B_HI);
#pragma unroll
            for (int ks = 0; ks < 8; ++ks) {
                int kch = (ks * 16 + khalf) >> 3;
                uint32_t a[2][4];
#pragma unroll
                for (int mt = 0; mt < 2; ++mt) {
                    int row = wm * 32 + mt * 16 + rbase;
                    ldm4(a[mt], aBase + row * 256 +
                                ((((kch & 7) ^ (row & 7)) << 4) + ((kch & 8) << 4)));
                }
                uint32_t b[3][4];
#pragma unroll
                for (int bt = 0; bt < 3; ++bt) {
                    int row = wn * 48 + bt * 16 + rbase;
                    ldm4(b[bt], bBase + row * 256 +
                                ((((kch & 7) ^ (row & 7)) << 4) + ((kch & 8) << 4)));
                }
#pragma unroll
                for (int mt = 0; mt < 2; ++mt)
#pragma unroll
                    for (int nt = 0; nt < 6; ++nt)
                        mma16816(acc[mt][nt], a[mt],
                                 b[nt >> 1][nt & 1], b[nt >> 1][(nt & 1) + 2]);
            }
        }

        int gr = lane >> 2, gc = (lane & 3) * 2;
#pragma unroll
        for (int nt = 0; nt < 6; ++nt) {
            int col = n0 + wn * 48 + nt * 8 + gc;
            float b0 = g_bsm[col], b1 = g_bsm[col + 1];
#pragma unroll
            for (int mt = 0; mt < 2; ++mt) {
                int row = m0 + wm * 32 + mt * 16 + gr;
                float2 v0 = { acc[mt][nt][0] + b0, acc[mt][nt][1] + b1 };
                float2 v1 = { acc[mt][nt][2] + b0, acc[mt][nt][3] + b1 };
                *(float2*)&g_S[(size_t)row * 192 + col]       = v0;
                *(float2*)&g_S[(size_t)(row + 8) * 192 + col] = v1;
            }
        }
    }
}

// ---------------- counting sort: hierarchical parallel scan + scatter ----------------
// S1: 64 blocks x 128 thr — local exclusive scan of 128 hist entries + block sum
__global__ void k_scan1() {
    __shared__ int wsum[4];
    int b = blockIdx.x, t = threadIdx.x, lane = t & 31, w = t >> 5;
    int i = b * 128 + t;
    int v = g_hist[i];
    int p = v;
#pragma unroll
    for (int off = 1; off < 32; off <<= 1) {
        int n = __shfl_up_sync(0xffffffffu, p, off);
        if (lane >= off) p += n;
    }
    if (lane == 31) wsum[w] = p;
    __syncthreads();
    int wb = 0;
#pragma unroll
    for (int k = 0; k < 4; ++k) wb += (k < w) ? wsum[k] : 0;
    g_off[i] = p - v + wb;            // exclusive within block
    if (t == 127) g_bs[b] = p + wb;   // block total
}
// S2: 1 warp — exclusive scan of 64 block sums
__global__ void k_scan2() {
    int lane = threadIdx.x;           // 32 threads
    int a = g_bs[2 * lane], b = g_bs[2 * lane + 1];
    int s = a + b;
    int p = s;
#pragma unroll
    for (int off = 1; off < 32; off <<= 1) {
        int n = __shfl_up_sync(0xffffffffu, p, off);
        if (lane >= off) p += n;
    }
    int excl = p - s;
    g_bspre[2 * lane]     = excl;
    g_bspre[2 * lane + 1] = excl + a;
    if (lane == 0) g_off[NN] = EE;
}
// S3: 64 blocks x 128 thr — add block prefix, fill cursor
__global__ void k_scan3() {
    int b = blockIdx.x, t = threadIdx.x;
    int i = b * 128 + t;
    int off = g_off[i] + g_bspre[b];
    g_off[i]    = off;
    g_cursor[i] = off;
}
__global__ void k_scatter(const int* __restrict__ src) {
    int e = blockIdx.x * blockDim.x + threadIdx.x;
    if (e < EE) {
        int p = atomicAdd(&g_cursor[src[e]], 1);
        g_sorted[p] = e;
    }
}

// ---------------- edge kernel (fp16 A) ----------------
__global__ __launch_bounds__(64) void k_edge(const int* __restrict__ dst,
                                             float* __restrict__ out) {
    int n = blockIdx.x;
    int beg = g_off[n], end = g_off[n + 1];
    if (beg == end) return;
    int j = threadIdx.x;
    int lane = j & 31;

    float Areg[64];
    const __half* Ap = &g_A[(size_t)n * RDIM + j];
#pragma unroll
    for (int d = 0; d < 64; ++d) Areg[d] = __half2float(Ap[d * 64]);

    float cj = g_Call[j] + g_S[(size_t)n * 192 + 64 + j];

    for (int idx = beg; idx < end; ++idx) {
        int e = g_sorted[idx];
        int m = dst[e];
        const float* Sp = &g_S[(size_t)m * 192];
        float p2lo = Sp[lane];
        float p2hi = Sp[32 + lane];
        float acc = cj + Sp[128 + j];
#pragma unroll
        for (int d = 0; d < 32; ++d)
            acc += Areg[d] * __shfl_sync(0xffffffffu, p2lo, d);
#pragma unroll
        for (int d = 0; d < 32; ++d)
            acc += Areg[32 + d] * __shfl_sync(0xffffffffu, p2hi, d);
        out[(size_t)e * 64 + j] = fmaxf(acc, 0.f);
    }
}

// ---------------- launch ----------------
extern "C" void kernel_launch(void* const* d_in, const int* in_sizes, int n_in,
                              void* d_out, int out_size) {
    const float* h     = (const float*)d_in[0];
    const int*   src   = (const int*)  d_in[1];
    const int*   dst   = (const int*)  d_in[2];
    const float* p1w   = (const float*)d_in[3];
    const float* p1b   = (const float*)d_in[4];
    const float* p2w   = (const float*)d_in[5];
    const float* p2b   = (const float*)d_in[6];
    const float* convw = (const float*)d_in[7];
    const float* convb = (const float*)d_in[8];
    const float* e2w   = (const float*)d_in[9];
    const float* e2b   = (const float*)d_in[10];
    const float* e3w   = (const float*)d_in[11];
    const float* e3b   = (const float*)d_in[12];
    const float* gam   = (const float*)d_in[13];
    const float* bet   = (const float*)d_in[14];
    const float* mean  = (const float*)d_in[15];
    const float* var   = (const float*)d_in[16];
    float* out = (float*)d_out;

    cudaFuncSetAttribute(k_fold1,      cudaFuncAttributeMaxDynamicSharedMemorySize, FOLD1_SMEM);
    cudaFuncSetAttribute(k_gemm_fused, cudaFuncAttributeMaxDynamicSharedMemorySize, FU_SMEM);

    k_fold1<<<64, 256, FOLD1_SMEM>>>(p1w, p1b, e3w, gam, var);
    k_fold2<<<192, 128>>>(p2w, p2b, convw, e2w, gam, var, e2b, e3b, convb, bet, mean);
    k_convert_h<<<512, 256>>>(h, src);
    k_scan1<<<64, 128>>>();
    k_scan2<<<1, 32>>>();
    k_scan3<<<64, 128>>>();
    k_scatter<<<(EE + 255) / 256, 256>>>(src);
    k_gemm_fused<<<128 + NN / 128 * (RDIM / 128), 256, FU_SMEM>>>();
    k_edge<<<NN, 64>>>(dst, out);
}